// round 5
// baseline (speedup 1.0000x reference)
#include <cuda_runtime.h>
#include <math.h>

#define NMAX 50000
#define KD 128

__device__ float g_h[(size_t)NMAX * KD];
__device__ float g_agg[(size_t)NMAX * KD];
__device__ float g_o0[(size_t)NMAX * KD];

// ---------------- tf32 helpers ----------------
__device__ __forceinline__ float tf32_rna(float x) {
    unsigned u;
    asm("cvt.rna.tf32.f32 %0, %1;" : "=r"(u) : "f"(x));
    return __uint_as_float(u);
}

__device__ __forceinline__ void mma8(float* d, float a0, float a1, float a2, float a3,
                                     float b0, float b1)
{
    asm("mma.sync.aligned.m16n8k8.row.col.f32.tf32.tf32.f32 "
        "{%0,%1,%2,%3}, {%4,%5,%6,%7}, {%8,%9}, {%0,%1,%2,%3};"
        : "+f"(d[0]), "+f"(d[1]), "+f"(d[2]), "+f"(d[3])
        : "r"(__float_as_uint(a0)), "r"(__float_as_uint(a1)),
          "r"(__float_as_uint(a2)), "r"(__float_as_uint(a3)),
          "r"(__float_as_uint(b0)), "r"(__float_as_uint(b1)));
}

// Fragment-order smem layouts:
//  A (hi & lo):  AH[(t*16+q)*128 + lane*4 + slot]
//    t = m-tile (16 rows), q = k-chunk (8 ks), lane holds
//    a0=(r,k0) a1=(r+8,k0) a2=(r,k0+4) a3=(r+8,k0+4) with r=lane>>2, k0=lane&3
//  W packed:     WS[(nt*16+q)*128 + lane*4 + {bh0,bh1,bl0,bl1}]
//    nt = n-tile (8 cols), lane holds b0=(k=lane&3,n=lane>>2), b1=(k+4,n)

// ---- stage W[FOUT][128] into split fragment layout ----
template <int FOUT>
__device__ __forceinline__ void stage_w(const float* __restrict__ W, float* __restrict__ WS,
                                        int tid)
{
    for (int i = tid; i < FOUT * 32; i += 256) {
        int o = i >> 5, l = i & 31;
        float4 w = reinterpret_cast<const float4*>(W)[i];
        int q = l >> 1, sp = l & 1;
        int base = ((o >> 3) * 16 + q) * 128 + ((o & 7) << 4); // ((o&7)*4)*4
        float wv[4] = {w.x, w.y, w.z, w.w};
        #pragma unroll
        for (int j = 0; j < 4; ++j) {
            float hi = tf32_rna(wv[j]);
            float lo = wv[j] - hi;
            WS[base + j * 4 + sp]     = hi;
            WS[base + j * 4 + 2 + sp] = lo;
        }
    }
}

// ---- stage A rows [64][128] into split fragment layout ----
// MODE 0: raw (fc pass 0); MODE 1: sqrt (fc pass 1); MODE 2: raw + sumsq atomics (pool)
template <int MODE>
__device__ __forceinline__ void stage_a(const float* __restrict__ Ain, float* __restrict__ AH,
                                        float* __restrict__ AL, float* __restrict__ sumsq,
                                        int tid, int m0, int n)
{
    float part = 0.f;
    int row = tid & 63;
    #pragma unroll
    for (int it = 0; it < 8; ++it) {
        int l = (tid >> 6) + it * 4;
        int m = m0 + row;
        float4 v = make_float4(0.f, 0.f, 0.f, 0.f);
        if (m < n) v = reinterpret_cast<const float4*>(Ain)[(size_t)m * 32 + l];
        if (MODE == 1) {
            v.x = sqrtf(v.x); v.y = sqrtf(v.y); v.z = sqrtf(v.z); v.w = sqrtf(v.w);
        }
        if (MODE == 2)
            part += v.x * v.x + v.y * v.y + v.z * v.z + v.w * v.w;
        int t = row >> 4, r = row & 15;
        int q = l >> 1;
        int slot = (r >> 3) + ((l & 1) << 1);
        int base = (t * 16 + q) * 128 + ((r & 7) << 4) + slot;
        float vv[4] = {v.x, v.y, v.z, v.w};
        #pragma unroll
        for (int j = 0; j < 4; ++j) {
            float hi = tf32_rna(vv[j]);
            AH[base + j * 4] = hi;
            AL[base + j * 4] = vv[j] - hi;
        }
    }
    if (MODE == 2) atomicAdd(&sumsq[row], part);
}

// ---- warp mainloop: accumulate 32x(NTW*8) tile over K=128 with 3xtf32 ----
template <int NTW>
__device__ __forceinline__ void mma_loop(const float* __restrict__ AH,
                                         const float* __restrict__ AL,
                                         const float* __restrict__ WS,
                                         int wr, int wc, int lane,
                                         float acc[2][NTW][4])
{
    #pragma unroll 4
    for (int q = 0; q < 16; ++q) {
        float4 ah[2], al[2];
        #pragma unroll
        for (int mt = 0; mt < 2; ++mt) {
            int t = wr * 2 + mt;
            ah[mt] = *reinterpret_cast<const float4*>(&AH[(t * 16 + q) * 128 + lane * 4]);
            al[mt] = *reinterpret_cast<const float4*>(&AL[(t * 16 + q) * 128 + lane * 4]);
        }
        float4 wv[NTW];
        #pragma unroll
        for (int nl = 0; nl < NTW; ++nl) {
            int nt = wc * NTW + nl;
            wv[nl] = *reinterpret_cast<const float4*>(&WS[(nt * 16 + q) * 128 + lane * 4]);
        }
        // hi*bh (independent accs), then lo*bh, then hi*bl
        #pragma unroll
        for (int mt = 0; mt < 2; ++mt)
            #pragma unroll
            for (int nl = 0; nl < NTW; ++nl)
                mma8(acc[mt][nl], ah[mt].x, ah[mt].y, ah[mt].z, ah[mt].w, wv[nl].x, wv[nl].y);
        #pragma unroll
        for (int mt = 0; mt < 2; ++mt)
            #pragma unroll
            for (int nl = 0; nl < NTW; ++nl)
                mma8(acc[mt][nl], al[mt].x, al[mt].y, al[mt].z, al[mt].w, wv[nl].x, wv[nl].y);
        #pragma unroll
        for (int mt = 0; mt < 2; ++mt)
            #pragma unroll
            for (int nl = 0; nl < NTW; ++nl)
                mma8(acc[mt][nl], ah[mt].x, ah[mt].y, ah[mt].z, ah[mt].w, wv[nl].z, wv[nl].w);
    }
}

// =====================================================================
// pool GEMM + fused L2-norm (epilogue scale) + relu
// block 64 x 128, 256 threads (8 warps = 2m x 4n), warp tile 32x32
// =====================================================================
__global__ __launch_bounds__(256, 1)
void pool_gemm(const float* __restrict__ X, const float* __restrict__ W,
               const float* __restrict__ B, float* __restrict__ H, int n)
{
    extern __shared__ float sm[];
    float* AH = sm;                  // 8192
    float* AL = AH + 8192;           // 8192
    float* WS = AL + 8192;           // 32768
    float* ss = WS + 32768;          // 64

    const int tid = threadIdx.x;
    const int warp = tid >> 5, lane = tid & 31;
    const int m0 = blockIdx.x * 64;

    if (tid < 64) ss[tid] = 0.f;
    __syncthreads();

    stage_w<128>(W, WS, tid);
    stage_a<2>(X, AH, AL, ss, tid, m0, n);
    __syncthreads();

    const int wr = warp >> 2, wc = warp & 3;
    float acc[2][4][4];
    #pragma unroll
    for (int a = 0; a < 2; ++a)
        #pragma unroll
        for (int b = 0; b < 4; ++b)
            #pragma unroll
            for (int c = 0; c < 4; ++c) acc[a][b][c] = 0.f;

    mma_loop<4>(AH, AL, WS, wr, wc, lane, acc);

    // epilogue
    #pragma unroll
    for (int mt = 0; mt < 2; ++mt) {
        #pragma unroll
        for (int rh = 0; rh < 2; ++rh) {
            int rloc = wr * 32 + mt * 16 + (lane >> 2) + rh * 8;
            int m = m0 + rloc;
            if (m >= n) continue;
            float inv = 1.0f / fmaxf(sqrtf(ss[rloc]), 1e-12f);
            #pragma unroll
            for (int nl = 0; nl < 4; ++nl) {
                int col = (wc * 4 + nl) * 8 + ((lane & 3) << 1);
                float2 r;
                r.x = fmaxf(fmaf(acc[mt][nl][rh * 2 + 0], inv, B[col]), 0.f);
                r.y = fmaxf(fmaf(acc[mt][nl][rh * 2 + 1], inv, B[col + 1]), 0.f);
                *reinterpret_cast<float2*>(&H[(size_t)m * 128 + col]) = r;
            }
        }
    }
}

// =====================================================================
// fused fc (two-pass): acc = H.W1^T + sqrt(G).W2^T ; OUT = act(acc+B1+B2)
// =====================================================================
template <int FOUT, bool RELU>
__global__ __launch_bounds__(256, 1)
void fc_gemm(const float* __restrict__ Hin, const float* __restrict__ G,
             const float* __restrict__ W1, const float* __restrict__ W2,
             const float* __restrict__ B1, const float* __restrict__ B2,
             float* __restrict__ OUT, int n)
{
    constexpr int NTW = FOUT / 32;
    extern __shared__ float sm[];
    float* AH = sm;
    float* AL = AH + 8192;
    float* WS = AL + 8192;          // FOUT*256 floats

    const int tid = threadIdx.x;
    const int warp = tid >> 5, lane = tid & 31;
    const int m0 = blockIdx.x * 64;
    const int wr = warp >> 2, wc = warp & 3;

    float acc[2][NTW][4];
    #pragma unroll
    for (int a = 0; a < 2; ++a)
        #pragma unroll
        for (int b = 0; b < NTW; ++b)
            #pragma unroll
            for (int c = 0; c < 4; ++c) acc[a][b][c] = 0.f;

    // pass 0
    stage_w<FOUT>(W1, WS, tid);
    stage_a<0>(Hin, AH, AL, nullptr, tid, m0, n);
    __syncthreads();
    mma_loop<NTW>(AH, AL, WS, wr, wc, lane, acc);
    __syncthreads();

    // pass 1
    stage_w<FOUT>(W2, WS, tid);
    stage_a<1>(G, AH, AL, nullptr, tid, m0, n);
    __syncthreads();
    mma_loop<NTW>(AH, AL, WS, wr, wc, lane, acc);

    #pragma unroll
    for (int mt = 0; mt < 2; ++mt) {
        #pragma unroll
        for (int rh = 0; rh < 2; ++rh) {
            int rloc = wr * 32 + mt * 16 + (lane >> 2) + rh * 8;
            int m = m0 + rloc;
            if (m >= n) continue;
            #pragma unroll
            for (int nl = 0; nl < NTW; ++nl) {
                int col = (wc * NTW + nl) * 8 + ((lane & 3) << 1);
                float2 r;
                r.x = acc[mt][nl][rh * 2 + 0] + B1[col] + B2[col];
                r.y = acc[mt][nl][rh * 2 + 1] + B1[col + 1] + B2[col + 1];
                if (RELU) { r.x = fmaxf(r.x, 0.f); r.y = fmaxf(r.y, 0.f); }
                *reinterpret_cast<float2*>(&OUT[(size_t)m * FOUT + col]) = r;
            }
        }
    }
}

// =====================================================================
// SpMM scatter: AGG[dst,:] += val * H[src,:]^2   (warp/edge, red.v4)
// =====================================================================
__global__ __launch_bounds__(256)
void spmm_kernel(const int* __restrict__ src, const int* __restrict__ dst,
                 const float* __restrict__ val, const float* __restrict__ Hm,
                 float* __restrict__ AGG, int E)
{
    int gw = (int)((blockIdx.x * 256u + threadIdx.x) >> 5);
    int lane = threadIdx.x & 31;
    if (gw >= E) return;
    int s = src[gw];
    int d = dst[gw];
    float v = val[gw];
    float4 h = reinterpret_cast<const float4*>(Hm)[(size_t)s * 32 + lane];
    float4 r;
    r.x = h.x * h.x * v;
    r.y = h.y * h.y * v;
    r.z = h.z * h.z * v;
    r.w = h.w * h.w * v;
    float* p = AGG + (size_t)d * 128 + lane * 4;
    asm volatile("red.global.add.v4.f32 [%0], {%1, %2, %3, %4};"
                 :: "l"(p), "f"(r.x), "f"(r.y), "f"(r.z), "f"(r.w) : "memory");
}

__global__ void zero_kernel(float4* __restrict__ p, int n4)
{
    int i = blockIdx.x * blockDim.x + threadIdx.x;
    int stride = gridDim.x * blockDim.x;
    float4 z = make_float4(0.f, 0.f, 0.f, 0.f);
    for (; i < n4; i += stride) p[i] = z;
}

// =====================================================================
extern "C" void kernel_launch(void* const* d_in, const int* in_sizes, int n_in,
                              void* d_out, int out_size)
{
    const float* x     = (const float*)d_in[0];
    const int*   esrc  = (const int*)  d_in[1];
    const int*   edst  = (const int*)  d_in[2];
    const float* eval_ = (const float*)d_in[3];
    const float* pw0   = (const float*)d_in[4];
    const float* pb0   = (const float*)d_in[5];
    const float* f1w0  = (const float*)d_in[6];
    const float* f1b0  = (const float*)d_in[7];
    const float* f2w0  = (const float*)d_in[8];
    const float* f2b0  = (const float*)d_in[9];
    const float* pw1   = (const float*)d_in[10];
    const float* pb1   = (const float*)d_in[11];
    const float* f1w1  = (const float*)d_in[12];
    const float* f1b1  = (const float*)d_in[13];
    const float* f2w1  = (const float*)d_in[14];
    const float* f2b1  = (const float*)d_in[15];
    float* out = (float*)d_out;

    int n = in_sizes[0] / KD;
    int E = in_sizes[1];

    float *hP, *aP, *oP;
    cudaGetSymbolAddress((void**)&hP, g_h);
    cudaGetSymbolAddress((void**)&aP, g_agg);
    cudaGetSymbolAddress((void**)&oP, g_o0);

    const int POOL_SMEM  = (8192 * 2 + 32768 + 64) * 4;   // 196,864 B
    const int FC128_SMEM = (8192 * 2 + 32768) * 4;        // 196,608 B
    const int FC64_SMEM  = (8192 * 2 + 16384) * 4;        // 131,072 B
    cudaFuncSetAttribute(pool_gemm, cudaFuncAttributeMaxDynamicSharedMemorySize, POOL_SMEM);
    cudaFuncSetAttribute((const void*)fc_gemm<128, true>,
                         cudaFuncAttributeMaxDynamicSharedMemorySize, FC128_SMEM);
    cudaFuncSetAttribute((const void*)fc_gemm<64, false>,
                         cudaFuncAttributeMaxDynamicSharedMemorySize, FC64_SMEM);

    int mb = (n + 63) / 64;
    int sb = (int)(((long long)E * 32 + 255) / 256);

    // ---- layer 0 ----
    pool_gemm<<<mb, 256, POOL_SMEM>>>(x, pw0, pb0, hP, n);
    zero_kernel<<<2048, 256>>>((float4*)aP, n * 32);
    spmm_kernel<<<sb, 256>>>(esrc, edst, eval_, hP, aP, E);
    fc_gemm<128, true><<<mb, 256, FC128_SMEM>>>(hP, aP, f1w0, f2w0, f1b0, f2b0, oP, n);

    // ---- layer 1 ----
    pool_gemm<<<mb, 256, POOL_SMEM>>>(oP, pw1, pb1, hP, n);
    zero_kernel<<<2048, 256>>>((float4*)aP, n * 32);
    spmm_kernel<<<sb, 256>>>(esrc, edst, eval_, hP, aP, E);
    fc_gemm<64, false><<<mb, 256, FC64_SMEM>>>(hP, aP, f1w1, f2w1, f1b1, f2b1, out, n);
}

// round 7
// speedup vs baseline: 1.6591x; 1.6591x over previous
#include <cuda_runtime.h>
#include <math.h>

#define NMAX 50000
#define KD 128

__device__ float g_h[(size_t)NMAX * KD];
__device__ float g_agg[(size_t)NMAX * KD];
__device__ float g_o0[(size_t)NMAX * KD];

// fragment-ordered split weights (hi/lo packed per float4)
__device__ float g_wfp0[32768];
__device__ float g_wf10[32768];
__device__ float g_wf20[32768];
__device__ float g_wfp1[32768];
__device__ float g_wf11[16384];
__device__ float g_wf21[16384];

// ---------------- tf32 helpers ----------------
__device__ __forceinline__ float tf32_rna(float x) {
    unsigned u;
    asm("cvt.rna.tf32.f32 %0, %1;" : "=r"(u) : "f"(x));
    return __uint_as_float(u);
}

__device__ __forceinline__ void mma8(float* d, float a0, float a1, float a2, float a3,
                                     float b0, float b1)
{
    asm("mma.sync.aligned.m16n8k8.row.col.f32.tf32.tf32.f32 "
        "{%0,%1,%2,%3}, {%4,%5,%6,%7}, {%8,%9}, {%0,%1,%2,%3};"
        : "+f"(d[0]), "+f"(d[1]), "+f"(d[2]), "+f"(d[3])
        : "r"(__float_as_uint(a0)), "r"(__float_as_uint(a1)),
          "r"(__float_as_uint(a2)), "r"(__float_as_uint(a3)),
          "r"(__float_as_uint(b0)), "r"(__float_as_uint(b1)));
}

// =====================================================================
// one-shot weight split into fragment order.
// Output float4[idx], idx = (nt*16+q)*32 + lane, nt in [0, FOUT/8):
//   n = nt*8 + lane/4, k = q*8 + lane%4
//   {hi(W[n,k]), hi(W[n,k+4]), lo(W[n,k]), lo(W[n,k+4])}
// total = FOUT*64 output float4s.
// =====================================================================
__global__ void split_w(const float* __restrict__ W, float* __restrict__ WF, int total)
{
    int idx = blockIdx.x * 256 + threadIdx.x;
    if (idx >= total) return;
    int lane = idx & 31, blk = idx >> 5;
    int q = blk & 15, nt = blk >> 4;
    int n = nt * 8 + (lane >> 2), k = q * 8 + (lane & 3);
    float w0 = W[n * 128 + k], w1 = W[n * 128 + k + 4];
    float h0 = tf32_rna(w0), h1 = tf32_rna(w1);
    reinterpret_cast<float4*>(WF)[idx] = make_float4(h0, h1, w0 - h0, w1 - h1);
}

// ---- stage A rows [64][128] into fragment layout ----
// SPLIT=1: write hi->AH, lo->AL. SPLIT=0: write raw value (optionally sqrt) -> AH.
// MODE: 0 raw, 1 sqrt, 2 raw + sumsq atomic
template <int SPLIT, int MODE>
__device__ __forceinline__ void stage_a(const float* __restrict__ Ain, float* __restrict__ AH,
                                        float* __restrict__ AL, float* __restrict__ sumsq,
                                        int tid, int m0, int n)
{
    float part = 0.f;
    int row = tid & 63;
    #pragma unroll
    for (int it = 0; it < 8; ++it) {
        int l = (tid >> 6) + it * 4;
        int m = m0 + row;
        float4 v = make_float4(0.f, 0.f, 0.f, 0.f);
        if (m < n) v = reinterpret_cast<const float4*>(Ain)[(size_t)m * 32 + l];
        if (MODE == 1) {
            v.x = sqrtf(v.x); v.y = sqrtf(v.y); v.z = sqrtf(v.z); v.w = sqrtf(v.w);
        }
        if (MODE == 2)
            part += v.x * v.x + v.y * v.y + v.z * v.z + v.w * v.w;
        int t = row >> 4, r = row & 15;
        int q = l >> 1;
        int slot = (r >> 3) + ((l & 1) << 1);
        int base = (t * 16 + q) * 128 + ((r & 7) << 4) + slot;
        float vv[4] = {v.x, v.y, v.z, v.w};
        #pragma unroll
        for (int j = 0; j < 4; ++j) {
            if (SPLIT) {
                float hi = tf32_rna(vv[j]);
                AH[base + j * 4] = hi;
                AL[base + j * 4] = vv[j] - hi;
            } else {
                AH[base + j * 4] = vv[j];
            }
        }
    }
    if (MODE == 2) atomicAdd(&sumsq[row], part);
}

// =====================================================================
// pool GEMM + fused L2-norm + relu.  64 rows x 128 cols, 256 thr,
// 8 warps (2m x 4n), W fragments streamed from global (L2-resident).
// =====================================================================
__global__ __launch_bounds__(256, 2)
void pool_gemm(const float* __restrict__ X, const float* __restrict__ WF,
               const float* __restrict__ B, float* __restrict__ H, int n)
{
    extern __shared__ float sm[];
    float* AH = sm;                  // 8192
    float* AL = AH + 8192;           // 8192
    float* ss = AL + 8192;           // 64

    const int tid = threadIdx.x;
    const int warp = tid >> 5, lane = tid & 31;
    const int m0 = blockIdx.x * 64;

    if (tid < 64) ss[tid] = 0.f;
    __syncthreads();
    stage_a<1, 2>(X, AH, AL, ss, tid, m0, n);
    __syncthreads();

    const int wr = warp >> 2, wc = warp & 3;
    const float4* WF4 = reinterpret_cast<const float4*>(WF);

    float acc[2][4][4];
    #pragma unroll
    for (int a = 0; a < 2; ++a)
        #pragma unroll
        for (int b = 0; b < 4; ++b)
            #pragma unroll
            for (int c = 0; c < 4; ++c) acc[a][b][c] = 0.f;

    #pragma unroll 2
    for (int q = 0; q < 16; ++q) {
        float4 ah[2], al[2];
        #pragma unroll
        for (int mt = 0; mt < 2; ++mt) {
            int t = wr * 2 + mt;
            ah[mt] = *reinterpret_cast<const float4*>(&AH[(t * 16 + q) * 128 + lane * 4]);
            al[mt] = *reinterpret_cast<const float4*>(&AL[(t * 16 + q) * 128 + lane * 4]);
        }
        float4 wv[4];
        #pragma unroll
        for (int nl = 0; nl < 4; ++nl)
            wv[nl] = __ldg(&WF4[((wc * 4 + nl) * 16 + q) * 32 + lane]);

        #pragma unroll
        for (int mt = 0; mt < 2; ++mt)
            #pragma unroll
            for (int nl = 0; nl < 4; ++nl)
                mma8(acc[mt][nl], ah[mt].x, ah[mt].y, ah[mt].z, ah[mt].w, wv[nl].x, wv[nl].y);
        #pragma unroll
        for (int mt = 0; mt < 2; ++mt)
            #pragma unroll
            for (int nl = 0; nl < 4; ++nl)
                mma8(acc[mt][nl], al[mt].x, al[mt].y, al[mt].z, al[mt].w, wv[nl].x, wv[nl].y);
        #pragma unroll
        for (int mt = 0; mt < 2; ++mt)
            #pragma unroll
            for (int nl = 0; nl < 4; ++nl)
                mma8(acc[mt][nl], ah[mt].x, ah[mt].y, ah[mt].z, ah[mt].w, wv[nl].z, wv[nl].w);
    }

    #pragma unroll
    for (int mt = 0; mt < 2; ++mt) {
        #pragma unroll
        for (int rh = 0; rh < 2; ++rh) {
            int rloc = wr * 32 + mt * 16 + (lane >> 2) + rh * 8;
            int m = m0 + rloc;
            if (m >= n) continue;
            float inv = 1.0f / fmaxf(sqrtf(ss[rloc]), 1e-12f);
            #pragma unroll
            for (int nl = 0; nl < 4; ++nl) {
                int col = (wc * 4 + nl) * 8 + ((lane & 3) << 1);
                float2 r;
                r.x = fmaxf(fmaf(acc[mt][nl][rh * 2 + 0], inv, B[col]), 0.f);
                r.y = fmaxf(fmaf(acc[mt][nl][rh * 2 + 1], inv, B[col + 1]), 0.f);
                *reinterpret_cast<float2*>(&H[(size_t)m * 128 + col]) = r;
            }
        }
    }
}

// =====================================================================
// fused fc, single pass: acc = H.W1^T + sqrt(G).W2^T ; OUT = act(acc+B1+B2)
// smem: AH/AL (H split) + GR (sqrt(G) raw, split on the fly)
// =====================================================================
template <int FOUT, bool RELU>
__global__ __launch_bounds__(256, 2)
void fc_gemm(const float* __restrict__ Hin, const float* __restrict__ G,
             const float* __restrict__ W1F, const float* __restrict__ W2F,
             const float* __restrict__ B1, const float* __restrict__ B2,
             float* __restrict__ OUT, int n)
{
    constexpr int NTW = FOUT / 32;
    extern __shared__ float sm[];
    float* AH = sm;
    float* AL = AH + 8192;
    float* GR = AL + 8192;

    const int tid = threadIdx.x;
    const int warp = tid >> 5, lane = tid & 31;
    const int m0 = blockIdx.x * 64;
    const int wr = warp >> 2, wc = warp & 3;

    stage_a<1, 0>(Hin, AH, AL, nullptr, tid, m0, n);
    stage_a<0, 1>(G, GR, nullptr, nullptr, tid, m0, n);
    __syncthreads();

    const float4* W1_4 = reinterpret_cast<const float4*>(W1F);
    const float4* W2_4 = reinterpret_cast<const float4*>(W2F);

    float acc[2][NTW][4];
    #pragma unroll
    for (int a = 0; a < 2; ++a)
        #pragma unroll
        for (int b = 0; b < NTW; ++b)
            #pragma unroll
            for (int c = 0; c < 4; ++c) acc[a][b][c] = 0.f;

    #pragma unroll 2
    for (int q = 0; q < 16; ++q) {
        float4 ah[2], al[2], gh[2], gl[2];
        #pragma unroll
        for (int mt = 0; mt < 2; ++mt) {
            int t = wr * 2 + mt;
            int off = (t * 16 + q) * 128 + lane * 4;
            ah[mt] = *reinterpret_cast<const float4*>(&AH[off]);
            al[mt] = *reinterpret_cast<const float4*>(&AL[off]);
            float4 g = *reinterpret_cast<const float4*>(&GR[off]);
            gh[mt].x = tf32_rna(g.x); gh[mt].y = tf32_rna(g.y);
            gh[mt].z = tf32_rna(g.z); gh[mt].w = tf32_rna(g.w);
            gl[mt].x = g.x - gh[mt].x; gl[mt].y = g.y - gh[mt].y;
            gl[mt].z = g.z - gh[mt].z; gl[mt].w = g.w - gh[mt].w;
        }
        float4 w1[NTW], w2[NTW];
        #pragma unroll
        for (int nl = 0; nl < NTW; ++nl) {
            int fi = ((wc * NTW + nl) * 16 + q) * 32 + lane;
            w1[nl] = __ldg(&W1_4[fi]);
            w2[nl] = __ldg(&W2_4[fi]);
        }
        #pragma unroll
        for (int mt = 0; mt < 2; ++mt)
            #pragma unroll
            for (int nl = 0; nl < NTW; ++nl)
                mma8(acc[mt][nl], ah[mt].x, ah[mt].y, ah[mt].z, ah[mt].w, w1[nl].x, w1[nl].y);
        #pragma unroll
        for (int mt = 0; mt < 2; ++mt)
            #pragma unroll
            for (int nl = 0; nl < NTW; ++nl)
                mma8(acc[mt][nl], gh[mt].x, gh[mt].y, gh[mt].z, gh[mt].w, w2[nl].x, w2[nl].y);
        #pragma unroll
        for (int mt = 0; mt < 2; ++mt)
            #pragma unroll
            for (int nl = 0; nl < NTW; ++nl)
                mma8(acc[mt][nl], al[mt].x, al[mt].y, al[mt].z, al[mt].w, w1[nl].x, w1[nl].y);
        #pragma unroll
        for (int mt = 0; mt < 2; ++mt)
            #pragma unroll
            for (int nl = 0; nl < NTW; ++nl)
                mma8(acc[mt][nl], gl[mt].x, gl[mt].y, gl[mt].z, gl[mt].w, w2[nl].x, w2[nl].y);
        #pragma unroll
        for (int mt = 0; mt < 2; ++mt)
            #pragma unroll
            for (int nl = 0; nl < NTW; ++nl)
                mma8(acc[mt][nl], ah[mt].x, ah[mt].y, ah[mt].z, ah[mt].w, w1[nl].z, w1[nl].w);
        #pragma unroll
        for (int mt = 0; mt < 2; ++mt)
            #pragma unroll
            for (int nl = 0; nl < NTW; ++nl)
                mma8(acc[mt][nl], gh[mt].x, gh[mt].y, gh[mt].z, gh[mt].w, w2[nl].z, w2[nl].w);
    }

    #pragma unroll
    for (int mt = 0; mt < 2; ++mt) {
        #pragma unroll
        for (int rh = 0; rh < 2; ++rh) {
            int rloc = wr * 32 + mt * 16 + (lane >> 2) + rh * 8;
            int m = m0 + rloc;
            if (m >= n) continue;
            #pragma unroll
            for (int nl = 0; nl < NTW; ++nl) {
                int col = (wc * NTW + nl) * 8 + ((lane & 3) << 1);
                float2 r;
                r.x = acc[mt][nl][rh * 2 + 0] + B1[col] + B2[col];
                r.y = acc[mt][nl][rh * 2 + 1] + B1[col + 1] + B2[col + 1];
                if (RELU) { r.x = fmaxf(r.x, 0.f); r.y = fmaxf(r.y, 0.f); }
                *reinterpret_cast<float2*>(&OUT[(size_t)m * FOUT + col]) = r;
            }
        }
    }
}

// =====================================================================
// SpMM scatter: AGG[dst,:] += val * H[src,:]^2   (warp/edge, red.v4)
// =====================================================================
__global__ __launch_bounds__(256)
void spmm_kernel(const int* __restrict__ src, const int* __restrict__ dst,
                 const float* __restrict__ val, const float* __restrict__ Hm,
                 float* __restrict__ AGG, int E)
{
    int gw = (int)((blockIdx.x * 256u + threadIdx.x) >> 5);
    int lane = threadIdx.x & 31;
    if (gw >= E) return;
    int s = src[gw];
    int d = dst[gw];
    float v = val[gw];
    float4 h = reinterpret_cast<const float4*>(Hm)[(size_t)s * 32 + lane];
    float4 r;
    r.x = h.x * h.x * v;
    r.y = h.y * h.y * v;
    r.z = h.z * h.z * v;
    r.w = h.w * h.w * v;
    float* p = AGG + (size_t)d * 128 + lane * 4;
    asm volatile("red.global.add.v4.f32 [%0], {%1, %2, %3, %4};"
                 :: "l"(p), "f"(r.x), "f"(r.y), "f"(r.z), "f"(r.w) : "memory");
}

__global__ void zero_kernel(float4* __restrict__ p, int n4)
{
    int i = blockIdx.x * blockDim.x + threadIdx.x;
    int stride = gridDim.x * blockDim.x;
    float4 z = make_float4(0.f, 0.f, 0.f, 0.f);
    for (; i < n4; i += stride) p[i] = z;
}

// =====================================================================
extern "C" void kernel_launch(void* const* d_in, const int* in_sizes, int n_in,
                              void* d_out, int out_size)
{
    const float* x     = (const float*)d_in[0];
    const int*   esrc  = (const int*)  d_in[1];
    const int*   edst  = (const int*)  d_in[2];
    const float* eval_ = (const float*)d_in[3];
    const float* pw0   = (const float*)d_in[4];
    const float* pb0   = (const float*)d_in[5];
    const float* f1w0  = (const float*)d_in[6];
    const float* f1b0  = (const float*)d_in[7];
    const float* f2w0  = (const float*)d_in[8];
    const float* f2b0  = (const float*)d_in[9];
    const float* pw1   = (const float*)d_in[10];
    const float* pb1   = (const float*)d_in[11];
    const float* f1w1  = (const float*)d_in[12];
    const float* f1b1  = (const float*)d_in[13];
    const float* f2w1  = (const float*)d_in[14];
    const float* f2b1  = (const float*)d_in[15];
    float* out = (float*)d_out;

    int n = in_sizes[0] / KD;
    int E = in_sizes[1];

    float *hP, *aP, *oP;
    float *wp0, *w10, *w20, *wp1, *w11, *w21;
    cudaGetSymbolAddress((void**)&hP, g_h);
    cudaGetSymbolAddress((void**)&aP, g_agg);
    cudaGetSymbolAddress((void**)&oP, g_o0);
    cudaGetSymbolAddress((void**)&wp0, g_wfp0);
    cudaGetSymbolAddress((void**)&w10, g_wf10);
    cudaGetSymbolAddress((void**)&w20, g_wf20);
    cudaGetSymbolAddress((void**)&wp1, g_wfp1);
    cudaGetSymbolAddress((void**)&w11, g_wf11);
    cudaGetSymbolAddress((void**)&w21, g_wf21);

    const int POOL_SMEM = (8192 * 2 + 64) * 4;       // 65,792 B
    const int FC_SMEM   = (8192 * 3) * 4;            // 98,304 B
    cudaFuncSetAttribute(pool_gemm, cudaFuncAttributeMaxDynamicSharedMemorySize, POOL_SMEM);
    cudaFuncSetAttribute((const void*)fc_gemm<128, true>,
                         cudaFuncAttributeMaxDynamicSharedMemorySize, FC_SMEM);
    cudaFuncSetAttribute((const void*)fc_gemm<64, false>,
                         cudaFuncAttributeMaxDynamicSharedMemorySize, FC_SMEM);

    int mb = (n + 63) / 64;
    int sb = (int)(((long long)E * 32 + 255) / 256);

    // ---- one-shot weight splits (FOUT*64 output float4s each) ----
    split_w<<<32, 256>>>(pw0,  wp0, 128 * 64);
    split_w<<<32, 256>>>(f1w0, w10, 128 * 64);
    split_w<<<32, 256>>>(f2w0, w20, 128 * 64);
    split_w<<<32, 256>>>(pw1,  wp1, 128 * 64);
    split_w<<<16, 256>>>(f1w1, w11, 64 * 64);
    split_w<<<16, 256>>>(f2w1, w21, 64 * 64);

    // ---- layer 0 ----
    pool_gemm<<<mb, 256, POOL_SMEM>>>(x, wp0, pb0, hP, n);
    zero_kernel<<<2048, 256>>>((float4*)aP, n * 32);
    spmm_kernel<<<sb, 256>>>(esrc, edst, eval_, hP, aP, E);
    fc_gemm<128, true><<<mb, 256, FC_SMEM>>>(hP, aP, w10, w20, f1b0, f2b0, oP, n);

    // ---- layer 1 ----
    pool_gemm<<<mb, 256, POOL_SMEM>>>(oP, wp1, pb1, hP, n);
    zero_kernel<<<2048, 256>>>((float4*)aP, n * 32);
    spmm_kernel<<<sb, 256>>>(esrc, edst, eval_, hP, aP, E);
    fc_gemm<64, false><<<mb, 256, FC_SMEM>>>(hP, aP, w11, w21, f1b1, f2b1, out, n);
}

// round 8
// speedup vs baseline: 2.0275x; 1.2221x over previous
#include <cuda_runtime.h>
#include <math.h>

#define NMAX 50000
#define EMAX 800000
#define KD 128

__device__ float g_h[(size_t)NMAX * KD];
__device__ float g_agg[(size_t)NMAX * KD];
__device__ float g_o0[(size_t)NMAX * KD];

// fragment-ordered split weights (hi/lo packed per float4)
__device__ float g_wfp0[32768];
__device__ float g_wf10[32768];
__device__ float g_wf20[32768];
__device__ float g_wfp1[32768];
__device__ float g_wf11[16384];
__device__ float g_wf21[16384];

// CSR scratch (built once per call, reused by both layers)
__device__ int  g_cnt[NMAX];
__device__ int  g_rowptr[NMAX + 1];
__device__ int  g_cursor[NMAX];
__device__ int2 g_edata[EMAX];

// ---------------- tf32 helpers ----------------
__device__ __forceinline__ float tf32_rna(float x) {
    unsigned u;
    asm("cvt.rna.tf32.f32 %0, %1;" : "=r"(u) : "f"(x));
    return __uint_as_float(u);
}

__device__ __forceinline__ void mma8(float* d, float a0, float a1, float a2, float a3,
                                     float b0, float b1)
{
    asm("mma.sync.aligned.m16n8k8.row.col.f32.tf32.tf32.f32 "
        "{%0,%1,%2,%3}, {%4,%5,%6,%7}, {%8,%9}, {%0,%1,%2,%3};"
        : "+f"(d[0]), "+f"(d[1]), "+f"(d[2]), "+f"(d[3])
        : "r"(__float_as_uint(a0)), "r"(__float_as_uint(a1)),
          "r"(__float_as_uint(a2)), "r"(__float_as_uint(a3)),
          "r"(__float_as_uint(b0)), "r"(__float_as_uint(b1)));
}

// =====================================================================
// all 6 weight splits in ONE launch. job = blockIdx.y.
// Output float4[idx], idx = (nt*16+q)*32 + lane:
//   n = nt*8 + lane/4, k = q*8 + lane%4
//   {hi(W[n,k]), hi(W[n,k+4]), lo(W[n,k]), lo(W[n,k+4])}
// =====================================================================
__global__ void split_w6(const float* __restrict__ w0, const float* __restrict__ w1,
                         const float* __restrict__ w2, const float* __restrict__ w3,
                         const float* __restrict__ w4, const float* __restrict__ w5,
                         float* o0, float* o1, float* o2, float* o3, float* o4, float* o5)
{
    int j = blockIdx.y;
    const float* W;
    float* WF;
    int total;
    switch (j) {
        case 0: W = w0; WF = o0; total = 8192; break;
        case 1: W = w1; WF = o1; total = 8192; break;
        case 2: W = w2; WF = o2; total = 8192; break;
        case 3: W = w3; WF = o3; total = 8192; break;
        case 4: W = w4; WF = o4; total = 4096; break;
        default: W = w5; WF = o5; total = 4096; break;
    }
    int idx = blockIdx.x * 256 + threadIdx.x;
    if (idx >= total) return;
    int lane = idx & 31, blk = idx >> 5;
    int q = blk & 15, nt = blk >> 4;
    int n = nt * 8 + (lane >> 2), k = q * 8 + (lane & 3);
    float v0 = W[n * 128 + k], v1 = W[n * 128 + k + 4];
    float h0 = tf32_rna(v0), h1 = tf32_rna(v1);
    reinterpret_cast<float4*>(WF)[idx] = make_float4(h0, h1, v0 - h0, v1 - h1);
}

// ===================== CSR build =====================
__global__ void zero_cnt(int* __restrict__ cnt, int n)
{
    int i = blockIdx.x * blockDim.x + threadIdx.x;
    if (i < n) cnt[i] = 0;
}

__global__ void hist_kernel(const int* __restrict__ dst, int* __restrict__ cnt, int E)
{
    int i = blockIdx.x * blockDim.x + threadIdx.x;
    int stride = gridDim.x * blockDim.x;
    for (; i < E; i += stride) atomicAdd(&cnt[dst[i]], 1);
}

// single-block exclusive scan (warp-scan + smem partials), writes rowptr & cursor
__global__ void scan_kernel(const int* __restrict__ cnt, int* __restrict__ rowptr,
                            int* __restrict__ cursor, int n)
{
    __shared__ int wsum[32];
    __shared__ int carry;
    const int tid = threadIdx.x, lane = tid & 31, wid = tid >> 5;
    if (tid == 0) carry = 0;
    __syncthreads();
    for (int base = 0; base < n; base += 1024) {
        int v = (base + tid < n) ? cnt[base + tid] : 0;
        int x = v;
        #pragma unroll
        for (int off = 1; off < 32; off <<= 1) {
            int t = __shfl_up_sync(0xffffffffu, x, off);
            if (lane >= off) x += t;
        }
        if (lane == 31) wsum[wid] = x;
        __syncthreads();
        if (wid == 0) {
            int y = wsum[lane];
            #pragma unroll
            for (int off = 1; off < 32; off <<= 1) {
                int t = __shfl_up_sync(0xffffffffu, y, off);
                if (lane >= off) y += t;
            }
            wsum[lane] = y;
        }
        __syncthreads();
        int c = carry;
        int incl = x + (wid ? wsum[wid - 1] : 0);
        int excl = incl - v + c;
        if (base + tid < n) { rowptr[base + tid] = excl; cursor[base + tid] = excl; }
        __syncthreads();
        if (tid == 0) carry = c + wsum[31];
        __syncthreads();
    }
    if (tid == 0) rowptr[n] = carry;
}

__global__ void scatter_kernel(const int* __restrict__ src, const int* __restrict__ dst,
                               const float* __restrict__ val, int* __restrict__ cursor,
                               int2* __restrict__ edata, int E)
{
    int i = blockIdx.x * blockDim.x + threadIdx.x;
    int stride = gridDim.x * blockDim.x;
    for (; i < E; i += stride) {
        int d = dst[i];
        int pos = atomicAdd(&cursor[d], 1);
        edata[pos] = make_int2(src[i], __float_as_int(val[i]));
    }
}

// =====================================================================
// SpMM gather: AGG[r,:] = sum_{e in row r} val_e * H[src_e,:]^2
// one warp per dst row, no atomics, writes full rows (no pre-zero needed)
// =====================================================================
__global__ __launch_bounds__(256)
void spmm_gather(const int2* __restrict__ edata, const int* __restrict__ rowptr,
                 const float* __restrict__ Hm, float* __restrict__ AGG, int n)
{
    int gw = (int)((blockIdx.x * 256u + threadIdx.x) >> 5);
    int lane = threadIdx.x & 31;
    if (gw >= n) return;
    int e0 = rowptr[gw], e1 = rowptr[gw + 1];
    const float4* H4 = reinterpret_cast<const float4*>(Hm);
    float4 acc = make_float4(0.f, 0.f, 0.f, 0.f);
    int e = e0;
    for (; e + 1 < e1; e += 2) {
        int2 ea = __ldg(&edata[e]);
        int2 eb = __ldg(&edata[e + 1]);
        float va = __int_as_float(ea.y);
        float vb = __int_as_float(eb.y);
        float4 ha = __ldg(&H4[(size_t)ea.x * 32 + lane]);
        float4 hb = __ldg(&H4[(size_t)eb.x * 32 + lane]);
        acc.x = fmaf(va * ha.x, ha.x, acc.x);
        acc.y = fmaf(va * ha.y, ha.y, acc.y);
        acc.z = fmaf(va * ha.z, ha.z, acc.z);
        acc.w = fmaf(va * ha.w, ha.w, acc.w);
        acc.x = fmaf(vb * hb.x, hb.x, acc.x);
        acc.y = fmaf(vb * hb.y, hb.y, acc.y);
        acc.z = fmaf(vb * hb.z, hb.z, acc.z);
        acc.w = fmaf(vb * hb.w, hb.w, acc.w);
    }
    if (e < e1) {
        int2 ea = __ldg(&edata[e]);
        float va = __int_as_float(ea.y);
        float4 ha = __ldg(&H4[(size_t)ea.x * 32 + lane]);
        acc.x = fmaf(va * ha.x, ha.x, acc.x);
        acc.y = fmaf(va * ha.y, ha.y, acc.y);
        acc.z = fmaf(va * ha.z, ha.z, acc.z);
        acc.w = fmaf(va * ha.w, ha.w, acc.w);
    }
    reinterpret_cast<float4*>(AGG)[(size_t)gw * 32 + lane] = acc;
}

// ---- stage A rows [64][128] into fragment layout ----
template <int SPLIT, int MODE>
__device__ __forceinline__ void stage_a(const float* __restrict__ Ain, float* __restrict__ AH,
                                        float* __restrict__ AL, float* __restrict__ sumsq,
                                        int tid, int m0, int n)
{
    float part = 0.f;
    int row = tid & 63;
    #pragma unroll
    for (int it = 0; it < 8; ++it) {
        int l = (tid >> 6) + it * 4;
        int m = m0 + row;
        float4 v = make_float4(0.f, 0.f, 0.f, 0.f);
        if (m < n) v = reinterpret_cast<const float4*>(Ain)[(size_t)m * 32 + l];
        if (MODE == 1) {
            v.x = sqrtf(v.x); v.y = sqrtf(v.y); v.z = sqrtf(v.z); v.w = sqrtf(v.w);
        }
        if (MODE == 2)
            part += v.x * v.x + v.y * v.y + v.z * v.z + v.w * v.w;
        int t = row >> 4, r = row & 15;
        int q = l >> 1;
        int slot = (r >> 3) + ((l & 1) << 1);
        int base = (t * 16 + q) * 128 + ((r & 7) << 4) + slot;
        float vv[4] = {v.x, v.y, v.z, v.w};
        #pragma unroll
        for (int j = 0; j < 4; ++j) {
            if (SPLIT) {
                float hi = tf32_rna(vv[j]);
                AH[base + j * 4] = hi;
                AL[base + j * 4] = vv[j] - hi;
            } else {
                AH[base + j * 4] = vv[j];
            }
        }
    }
    if (MODE == 2) atomicAdd(&sumsq[row], part);
}

// =====================================================================
// pool GEMM + fused L2-norm + relu.
// =====================================================================
__global__ __launch_bounds__(256, 2)
void pool_gemm(const float* __restrict__ X, const float* __restrict__ WF,
               const float* __restrict__ B, float* __restrict__ H, int n)
{
    extern __shared__ float sm[];
    float* AH = sm;
    float* AL = AH + 8192;
    float* ss = AL + 8192;

    const int tid = threadIdx.x;
    const int warp = tid >> 5, lane = tid & 31;
    const int m0 = blockIdx.x * 64;

    if (tid < 64) ss[tid] = 0.f;
    __syncthreads();
    stage_a<1, 2>(X, AH, AL, ss, tid, m0, n);
    __syncthreads();

    const int wr = warp >> 2, wc = warp & 3;
    const float4* WF4 = reinterpret_cast<const float4*>(WF);

    float acc[2][4][4];
    #pragma unroll
    for (int a = 0; a < 2; ++a)
        #pragma unroll
        for (int b = 0; b < 4; ++b)
            #pragma unroll
            for (int c = 0; c < 4; ++c) acc[a][b][c] = 0.f;

    #pragma unroll 2
    for (int q = 0; q < 16; ++q) {
        float4 ah[2], al[2];
        #pragma unroll
        for (int mt = 0; mt < 2; ++mt) {
            int t = wr * 2 + mt;
            ah[mt] = *reinterpret_cast<const float4*>(&AH[(t * 16 + q) * 128 + lane * 4]);
            al[mt] = *reinterpret_cast<const float4*>(&AL[(t * 16 + q) * 128 + lane * 4]);
        }
        float4 wv[4];
        #pragma unroll
        for (int nl = 0; nl < 4; ++nl)
            wv[nl] = __ldg(&WF4[((wc * 4 + nl) * 16 + q) * 32 + lane]);

        #pragma unroll
        for (int mt = 0; mt < 2; ++mt)
            #pragma unroll
            for (int nl = 0; nl < 4; ++nl)
                mma8(acc[mt][nl], ah[mt].x, ah[mt].y, ah[mt].z, ah[mt].w, wv[nl].x, wv[nl].y);
        #pragma unroll
        for (int mt = 0; mt < 2; ++mt)
            #pragma unroll
            for (int nl = 0; nl < 4; ++nl)
                mma8(acc[mt][nl], al[mt].x, al[mt].y, al[mt].z, al[mt].w, wv[nl].x, wv[nl].y);
        #pragma unroll
        for (int mt = 0; mt < 2; ++mt)
            #pragma unroll
            for (int nl = 0; nl < 4; ++nl)
                mma8(acc[mt][nl], ah[mt].x, ah[mt].y, ah[mt].z, ah[mt].w, wv[nl].z, wv[nl].w);
    }

    #pragma unroll
    for (int mt = 0; mt < 2; ++mt) {
        #pragma unroll
        for (int rh = 0; rh < 2; ++rh) {
            int rloc = wr * 32 + mt * 16 + (lane >> 2) + rh * 8;
            int m = m0 + rloc;
            if (m >= n) continue;
            float inv = 1.0f / fmaxf(sqrtf(ss[rloc]), 1e-12f);
            #pragma unroll
            for (int nl = 0; nl < 4; ++nl) {
                int col = (wc * 4 + nl) * 8 + ((lane & 3) << 1);
                float2 r;
                r.x = fmaxf(fmaf(acc[mt][nl][rh * 2 + 0], inv, B[col]), 0.f);
                r.y = fmaxf(fmaf(acc[mt][nl][rh * 2 + 1], inv, B[col + 1]), 0.f);
                *reinterpret_cast<float2*>(&H[(size_t)m * 128 + col]) = r;
            }
        }
    }
}

// =====================================================================
// fused fc, single pass: acc = H.W1^T + sqrt(G).W2^T ; OUT = act(acc+B1+B2)
// =====================================================================
template <int FOUT, bool RELU>
__global__ __launch_bounds__(256, 2)
void fc_gemm(const float* __restrict__ Hin, const float* __restrict__ G,
             const float* __restrict__ W1F, const float* __restrict__ W2F,
             const float* __restrict__ B1, const float* __restrict__ B2,
             float* __restrict__ OUT, int n)
{
    constexpr int NTW = FOUT / 32;
    extern __shared__ float sm[];
    float* AH = sm;
    float* AL = AH + 8192;
    float* GR = AL + 8192;

    const int tid = threadIdx.x;
    const int warp = tid >> 5, lane = tid & 31;
    const int m0 = blockIdx.x * 64;
    const int wr = warp >> 2, wc = warp & 3;

    stage_a<1, 0>(Hin, AH, AL, nullptr, tid, m0, n);
    stage_a<0, 1>(G, GR, nullptr, nullptr, tid, m0, n);
    __syncthreads();

    const float4* W1_4 = reinterpret_cast<const float4*>(W1F);
    const float4* W2_4 = reinterpret_cast<const float4*>(W2F);

    float acc[2][NTW][4];
    #pragma unroll
    for (int a = 0; a < 2; ++a)
        #pragma unroll
        for (int b = 0; b < NTW; ++b)
            #pragma unroll
            for (int c = 0; c < 4; ++c) acc[a][b][c] = 0.f;

    #pragma unroll 2
    for (int q = 0; q < 16; ++q) {
        float4 ah[2], al[2], gh[2], gl[2];
        #pragma unroll
        for (int mt = 0; mt < 2; ++mt) {
            int t = wr * 2 + mt;
            int off = (t * 16 + q) * 128 + lane * 4;
            ah[mt] = *reinterpret_cast<const float4*>(&AH[off]);
            al[mt] = *reinterpret_cast<const float4*>(&AL[off]);
            float4 g = *reinterpret_cast<const float4*>(&GR[off]);
            gh[mt].x = tf32_rna(g.x); gh[mt].y = tf32_rna(g.y);
            gh[mt].z = tf32_rna(g.z); gh[mt].w = tf32_rna(g.w);
            gl[mt].x = g.x - gh[mt].x; gl[mt].y = g.y - gh[mt].y;
            gl[mt].z = g.z - gh[mt].z; gl[mt].w = g.w - gh[mt].w;
        }
        float4 w1[NTW], w2[NTW];
        #pragma unroll
        for (int nl = 0; nl < NTW; ++nl) {
            int fi = ((wc * NTW + nl) * 16 + q) * 32 + lane;
            w1[nl] = __ldg(&W1_4[fi]);
            w2[nl] = __ldg(&W2_4[fi]);
        }
        #pragma unroll
        for (int mt = 0; mt < 2; ++mt)
            #pragma unroll
            for (int nl = 0; nl < NTW; ++nl)
                mma8(acc[mt][nl], ah[mt].x, ah[mt].y, ah[mt].z, ah[mt].w, w1[nl].x, w1[nl].y);
        #pragma unroll
        for (int mt = 0; mt < 2; ++mt)
            #pragma unroll
            for (int nl = 0; nl < NTW; ++nl)
                mma8(acc[mt][nl], gh[mt].x, gh[mt].y, gh[mt].z, gh[mt].w, w2[nl].x, w2[nl].y);
        #pragma unroll
        for (int mt = 0; mt < 2; ++mt)
            #pragma unroll
            for (int nl = 0; nl < NTW; ++nl)
                mma8(acc[mt][nl], al[mt].x, al[mt].y, al[mt].z, al[mt].w, w1[nl].x, w1[nl].y);
        #pragma unroll
        for (int mt = 0; mt < 2; ++mt)
            #pragma unroll
            for (int nl = 0; nl < NTW; ++nl)
                mma8(acc[mt][nl], gl[mt].x, gl[mt].y, gl[mt].z, gl[mt].w, w2[nl].x, w2[nl].y);
        #pragma unroll
        for (int mt = 0; mt < 2; ++mt)
            #pragma unroll
            for (int nl = 0; nl < NTW; ++nl)
                mma8(acc[mt][nl], ah[mt].x, ah[mt].y, ah[mt].z, ah[mt].w, w1[nl].z, w1[nl].w);
        #pragma unroll
        for (int mt = 0; mt < 2; ++mt)
            #pragma unroll
            for (int nl = 0; nl < NTW; ++nl)
                mma8(acc[mt][nl], gh[mt].x, gh[mt].y, gh[mt].z, gh[mt].w, w2[nl].z, w2[nl].w);
    }

    #pragma unroll
    for (int mt = 0; mt < 2; ++mt) {
        #pragma unroll
        for (int rh = 0; rh < 2; ++rh) {
            int rloc = wr * 32 + mt * 16 + (lane >> 2) + rh * 8;
            int m = m0 + rloc;
            if (m >= n) continue;
            #pragma unroll
            for (int nl = 0; nl < NTW; ++nl) {
                int col = (wc * NTW + nl) * 8 + ((lane & 3) << 1);
                float2 r;
                r.x = acc[mt][nl][rh * 2 + 0] + B1[col] + B2[col];
                r.y = acc[mt][nl][rh * 2 + 1] + B1[col + 1] + B2[col + 1];
                if (RELU) { r.x = fmaxf(r.x, 0.f); r.y = fmaxf(r.y, 0.f); }
                *reinterpret_cast<float2*>(&OUT[(size_t)m * FOUT + col]) = r;
            }
        }
    }
}

// =====================================================================
extern "C" void kernel_launch(void* const* d_in, const int* in_sizes, int n_in,
                              void* d_out, int out_size)
{
    const float* x     = (const float*)d_in[0];
    const int*   esrc  = (const int*)  d_in[1];
    const int*   edst  = (const int*)  d_in[2];
    const float* eval_ = (const float*)d_in[3];
    const float* pw0   = (const float*)d_in[4];
    const float* pb0   = (const float*)d_in[5];
    const float* f1w0  = (const float*)d_in[6];
    const float* f1b0  = (const float*)d_in[7];
    const float* f2w0  = (const float*)d_in[8];
    const float* f2b0  = (const float*)d_in[9];
    const float* pw1   = (const float*)d_in[10];
    const float* pb1   = (const float*)d_in[11];
    const float* f1w1  = (const float*)d_in[12];
    const float* f1b1  = (const float*)d_in[13];
    const float* f2w1  = (const float*)d_in[14];
    const float* f2b1  = (const float*)d_in[15];
    float* out = (float*)d_out;

    int n = in_sizes[0] / KD;
    int E = in_sizes[1];

    float *hP, *aP, *oP;
    float *wp0, *w10, *w20, *wp1, *w11, *w21;
    int *cntP, *rpP, *curP;
    int2 *edP;
    cudaGetSymbolAddress((void**)&hP, g_h);
    cudaGetSymbolAddress((void**)&aP, g_agg);
    cudaGetSymbolAddress((void**)&oP, g_o0);
    cudaGetSymbolAddress((void**)&wp0, g_wfp0);
    cudaGetSymbolAddress((void**)&w10, g_wf10);
    cudaGetSymbolAddress((void**)&w20, g_wf20);
    cudaGetSymbolAddress((void**)&wp1, g_wfp1);
    cudaGetSymbolAddress((void**)&w11, g_wf11);
    cudaGetSymbolAddress((void**)&w21, g_wf21);
    cudaGetSymbolAddress((void**)&cntP, g_cnt);
    cudaGetSymbolAddress((void**)&rpP, g_rowptr);
    cudaGetSymbolAddress((void**)&curP, g_cursor);
    cudaGetSymbolAddress((void**)&edP, g_edata);

    const int POOL_SMEM = (8192 * 2 + 64) * 4;
    const int FC_SMEM   = (8192 * 3) * 4;
    cudaFuncSetAttribute(pool_gemm, cudaFuncAttributeMaxDynamicSharedMemorySize, POOL_SMEM);
    cudaFuncSetAttribute((const void*)fc_gemm<128, true>,
                         cudaFuncAttributeMaxDynamicSharedMemorySize, FC_SMEM);
    cudaFuncSetAttribute((const void*)fc_gemm<64, false>,
                         cudaFuncAttributeMaxDynamicSharedMemorySize, FC_SMEM);

    int mb = (n + 63) / 64;
    int gb = (n * 32 + 255) / 256;       // spmm_gather: warp per row

    // ---- weight splits (1 launch) + CSR build (4 launches) ----
    split_w6<<<dim3(32, 6), 256>>>(pw0, f1w0, f2w0, pw1, f1w1, f2w1,
                                   wp0, w10, w20, wp1, w11, w21);
    zero_cnt<<<(n + 255) / 256, 256>>>(cntP, n);
    hist_kernel<<<512, 512>>>(edst, cntP, E);
    scan_kernel<<<1, 1024>>>(cntP, rpP, curP, n);
    scatter_kernel<<<512, 512>>>(esrc, edst, eval_, curP, edP, E);

    // ---- layer 0 ----
    pool_gemm<<<mb, 256, POOL_SMEM>>>(x, wp0, pb0, hP, n);
    spmm_gather<<<gb, 256>>>(edP, rpP, hP, aP, n);
    fc_gemm<128, true><<<mb, 256, FC_SMEM>>>(hP, aP, w10, w20, f1b0, f2b0, oP, n);

    // ---- layer 1 ----
    pool_gemm<<<mb, 256, POOL_SMEM>>>(oP, wp1, pb1, hP, n);
    spmm_gather<<<gb, 256>>>(edP, rpP, hP, aP, n);
    fc_gemm<64, false><<<mb, 256, FC_SMEM>>>(hP, aP, w11, w21, f1b1, f2b1, out, n);
}

// round 9
// speedup vs baseline: 2.2042x; 1.0871x over previous
#include <cuda_runtime.h>
#include <math.h>

#define NMAX 50000
#define EMAX 800000
#define KD 128
#define SCAN_CH 1024

__device__ float g_h[(size_t)NMAX * KD];
__device__ float g_agg[(size_t)NMAX * KD];
__device__ float g_o0[(size_t)NMAX * KD];

// fragment-ordered split weights (hi/lo packed per float4)
__device__ float g_wfp0[32768];
__device__ float g_wf10[32768];
__device__ float g_wf20[32768];
__device__ float g_wfp1[32768];
__device__ float g_wf11[16384];
__device__ float g_wf21[16384];

// CSR scratch (built once per call, reused by both layers)
__device__ int  g_cnt[NMAX];
__device__ int  g_rowptr[NMAX + 1];
__device__ int  g_cursor[NMAX];
__device__ int  g_bsum[64];
__device__ int  g_boff[64];
__device__ int2 g_edata[EMAX];

// ---------------- tf32 helpers ----------------
__device__ __forceinline__ float tf32_rna(float x) {
    unsigned u;
    asm("cvt.rna.tf32.f32 %0, %1;" : "=r"(u) : "f"(x));
    return __uint_as_float(u);
}

__device__ __forceinline__ void mma8(float* d, float a0, float a1, float a2, float a3,
                                     float b0, float b1)
{
    asm("mma.sync.aligned.m16n8k8.row.col.f32.tf32.tf32.f32 "
        "{%0,%1,%2,%3}, {%4,%5,%6,%7}, {%8,%9}, {%0,%1,%2,%3};"
        : "+f"(d[0]), "+f"(d[1]), "+f"(d[2]), "+f"(d[3])
        : "r"(__float_as_uint(a0)), "r"(__float_as_uint(a1)),
          "r"(__float_as_uint(a2)), "r"(__float_as_uint(a3)),
          "r"(__float_as_uint(b0)), "r"(__float_as_uint(b1)));
}

// =====================================================================
// all 6 weight splits in ONE launch (blockIdx.y = job)
// =====================================================================
__global__ void split_w6(const float* __restrict__ w0, const float* __restrict__ w1,
                         const float* __restrict__ w2, const float* __restrict__ w3,
                         const float* __restrict__ w4, const float* __restrict__ w5,
                         float* o0, float* o1, float* o2, float* o3, float* o4, float* o5)
{
    int j = blockIdx.y;
    const float* W;
    float* WF;
    int total;
    switch (j) {
        case 0: W = w0; WF = o0; total = 8192; break;
        case 1: W = w1; WF = o1; total = 8192; break;
        case 2: W = w2; WF = o2; total = 8192; break;
        case 3: W = w3; WF = o3; total = 8192; break;
        case 4: W = w4; WF = o4; total = 4096; break;
        default: W = w5; WF = o5; total = 4096; break;
    }
    int idx = blockIdx.x * 256 + threadIdx.x;
    if (idx >= total) return;
    int lane = idx & 31, blk = idx >> 5;
    int q = blk & 15, nt = blk >> 4;
    int n = nt * 8 + (lane >> 2), k = q * 8 + (lane & 3);
    float v0 = W[n * 128 + k], v1 = W[n * 128 + k + 4];
    float h0 = tf32_rna(v0), h1 = tf32_rna(v1);
    reinterpret_cast<float4*>(WF)[idx] = make_float4(h0, h1, v0 - h0, v1 - h1);
}

// ===================== CSR build =====================
__global__ void zero_cnt(int* __restrict__ cnt, int n)
{
    int i = blockIdx.x * blockDim.x + threadIdx.x;
    if (i < n) cnt[i] = 0;
}

__global__ void hist_kernel(const int* __restrict__ dst, int* __restrict__ cnt, int E)
{
    int i = blockIdx.x * blockDim.x + threadIdx.x;
    int stride = gridDim.x * blockDim.x;
    for (; i < E; i += stride) atomicAdd(&cnt[dst[i]], 1);
}

// phase 1: per-chunk reduce (256 thr, 4 elems/thr over SCAN_CH chunk)
__global__ void scan_reduce(const int* __restrict__ cnt, int* __restrict__ bsum, int n)
{
    __shared__ int wsum[8];
    const int tid = threadIdx.x, lane = tid & 31, wid = tid >> 5;
    int base = blockIdx.x * SCAN_CH + tid * 4;
    int s = 0;
    #pragma unroll
    for (int j = 0; j < 4; ++j) {
        int i = base + j;
        s += (i < n) ? cnt[i] : 0;
    }
    #pragma unroll
    for (int off = 16; off > 0; off >>= 1)
        s += __shfl_xor_sync(0xffffffffu, s, off);
    if (lane == 0) wsum[wid] = s;
    __syncthreads();
    if (tid == 0) {
        int t = 0;
        #pragma unroll
        for (int w = 0; w < 8; ++w) t += wsum[w];
        bsum[blockIdx.x] = t;
    }
}

// phase 2: scan the <=64 block partials (one warp pass over 2 halves)
__global__ void scan_blocks(const int* __restrict__ bsum, int* __restrict__ boff,
                            int* __restrict__ rowptr, int nb, int n)
{
    const int tid = threadIdx.x;   // 64 threads
    __shared__ int tmp[64];
    int v = (tid < nb) ? bsum[tid] : 0;
    tmp[tid] = v;
    __syncthreads();
    if (tid == 0) {
        int run = 0;
        for (int i = 0; i < nb; ++i) { int c = tmp[i]; tmp[i] = run; run += c; }
        rowptr[n] = run;
    }
    __syncthreads();
    if (tid < nb) boff[tid] = tmp[tid];
}

// phase 3: per-chunk exclusive scan + block offset -> rowptr & cursor
__global__ void scan_final(const int* __restrict__ cnt, const int* __restrict__ boff,
                           int* __restrict__ rowptr, int* __restrict__ cursor, int n)
{
    __shared__ int wsum[8];
    const int tid = threadIdx.x, lane = tid & 31, wid = tid >> 5;
    int base = blockIdx.x * SCAN_CH + tid * 4;
    int c[4];
    int tsum = 0;
    #pragma unroll
    for (int j = 0; j < 4; ++j) {
        int i = base + j;
        c[j] = (i < n) ? cnt[i] : 0;
        tsum += c[j];
    }
    int x = tsum;
    #pragma unroll
    for (int off = 1; off < 32; off <<= 1) {
        int t = __shfl_up_sync(0xffffffffu, x, off);
        if (lane >= off) x += t;
    }
    if (lane == 31) wsum[wid] = x;
    __syncthreads();
    if (wid == 0 && lane < 8) {
        int y = wsum[lane];
        #pragma unroll
        for (int off = 1; off < 8; off <<= 1) {
            int t = __shfl_up_sync(0xffu, y, off);
            if (lane >= off) y += t;
        }
        wsum[lane] = y;
    }
    __syncthreads();
    int run = x - tsum + (wid ? wsum[wid - 1] : 0) + boff[blockIdx.x];
    #pragma unroll
    for (int j = 0; j < 4; ++j) {
        int i = base + j;
        if (i < n) { rowptr[i] = run; cursor[i] = run; }
        run += c[j];
    }
}

__global__ void scatter_kernel(const int* __restrict__ src, const int* __restrict__ dst,
                               const float* __restrict__ val, int* __restrict__ cursor,
                               int2* __restrict__ edata, int E)
{
    int i = blockIdx.x * blockDim.x + threadIdx.x;
    int stride = gridDim.x * blockDim.x;
    for (; i < E; i += stride) {
        int d = dst[i];
        int pos = atomicAdd(&cursor[d], 1);
        edata[pos] = make_int2(src[i], __float_as_int(val[i]));
    }
}

// =====================================================================
// SpMM gather: AGG[r,:] = sum_{e in row r} val_e * H[src_e,:]^2
// =====================================================================
__global__ __launch_bounds__(256)
void spmm_gather(const int2* __restrict__ edata, const int* __restrict__ rowptr,
                 const float* __restrict__ Hm, float* __restrict__ AGG, int n)
{
    int gw = (int)((blockIdx.x * 256u + threadIdx.x) >> 5);
    int lane = threadIdx.x & 31;
    if (gw >= n) return;
    int e0 = rowptr[gw], e1 = rowptr[gw + 1];
    const float4* H4 = reinterpret_cast<const float4*>(Hm);
    float4 acc = make_float4(0.f, 0.f, 0.f, 0.f);
    int e = e0;
    for (; e + 1 < e1; e += 2) {
        int2 ea = __ldg(&edata[e]);
        int2 eb = __ldg(&edata[e + 1]);
        float va = __int_as_float(ea.y);
        float vb = __int_as_float(eb.y);
        float4 ha = __ldg(&H4[(size_t)ea.x * 32 + lane]);
        float4 hb = __ldg(&H4[(size_t)eb.x * 32 + lane]);
        acc.x = fmaf(va * ha.x, ha.x, acc.x);
        acc.y = fmaf(va * ha.y, ha.y, acc.y);
        acc.z = fmaf(va * ha.z, ha.z, acc.z);
        acc.w = fmaf(va * ha.w, ha.w, acc.w);
        acc.x = fmaf(vb * hb.x, hb.x, acc.x);
        acc.y = fmaf(vb * hb.y, hb.y, acc.y);
        acc.z = fmaf(vb * hb.z, hb.z, acc.z);
        acc.w = fmaf(vb * hb.w, hb.w, acc.w);
    }
    if (e < e1) {
        int2 ea = __ldg(&edata[e]);
        float va = __int_as_float(ea.y);
        float4 ha = __ldg(&H4[(size_t)ea.x * 32 + lane]);
        acc.x = fmaf(va * ha.x, ha.x, acc.x);
        acc.y = fmaf(va * ha.y, ha.y, acc.y);
        acc.z = fmaf(va * ha.z, ha.z, acc.z);
        acc.w = fmaf(va * ha.w, ha.w, acc.w);
    }
    reinterpret_cast<float4*>(AGG)[(size_t)gw * 32 + lane] = acc;
}

// ---- stage A rows [64][128] into fragment layout ----
template <int SPLIT, int MODE>
__device__ __forceinline__ void stage_a(const float* __restrict__ Ain, float* __restrict__ AH,
                                        float* __restrict__ AL, float* __restrict__ sumsq,
                                        int tid, int m0, int n)
{
    float part = 0.f;
    int row = tid & 63;
    #pragma unroll
    for (int it = 0; it < 8; ++it) {
        int l = (tid >> 6) + it * 4;
        int m = m0 + row;
        float4 v = make_float4(0.f, 0.f, 0.f, 0.f);
        if (m < n) v = reinterpret_cast<const float4*>(Ain)[(size_t)m * 32 + l];
        if (MODE == 1) {
            v.x = sqrtf(v.x); v.y = sqrtf(v.y); v.z = sqrtf(v.z); v.w = sqrtf(v.w);
        }
        if (MODE == 2)
            part += v.x * v.x + v.y * v.y + v.z * v.z + v.w * v.w;
        int t = row >> 4, r = row & 15;
        int q = l >> 1;
        int slot = (r >> 3) + ((l & 1) << 1);
        int base = (t * 16 + q) * 128 + ((r & 7) << 4) + slot;
        float vv[4] = {v.x, v.y, v.z, v.w};
        #pragma unroll
        for (int j = 0; j < 4; ++j) {
            if (SPLIT) {
                float hi = tf32_rna(vv[j]);
                AH[base + j * 4] = hi;
                AL[base + j * 4] = vv[j] - hi;
            } else {
                AH[base + j * 4] = vv[j];
            }
        }
    }
    if (MODE == 2) atomicAdd(&sumsq[row], part);
}

// =====================================================================
// pool GEMM + fused L2-norm + relu.
// =====================================================================
__global__ __launch_bounds__(256, 2)
void pool_gemm(const float* __restrict__ X, const float* __restrict__ WF,
               const float* __restrict__ B, float* __restrict__ H, int n)
{
    extern __shared__ float sm[];
    float* AH = sm;
    float* AL = AH + 8192;
    float* ss = AL + 8192;

    const int tid = threadIdx.x;
    const int warp = tid >> 5, lane = tid & 31;
    const int m0 = blockIdx.x * 64;

    if (tid < 64) ss[tid] = 0.f;
    __syncthreads();
    stage_a<1, 2>(X, AH, AL, ss, tid, m0, n);
    __syncthreads();

    const int wr = warp >> 2, wc = warp & 3;
    const float4* WF4 = reinterpret_cast<const float4*>(WF);

    float acc[2][4][4];
    #pragma unroll
    for (int a = 0; a < 2; ++a)
        #pragma unroll
        for (int b = 0; b < 4; ++b)
            #pragma unroll
            for (int c = 0; c < 4; ++c) acc[a][b][c] = 0.f;

    #pragma unroll 2
    for (int q = 0; q < 16; ++q) {
        float4 ah[2], al[2];
        #pragma unroll
        for (int mt = 0; mt < 2; ++mt) {
            int t = wr * 2 + mt;
            ah[mt] = *reinterpret_cast<const float4*>(&AH[(t * 16 + q) * 128 + lane * 4]);
            al[mt] = *reinterpret_cast<const float4*>(&AL[(t * 16 + q) * 128 + lane * 4]);
        }
        float4 wv[4];
        #pragma unroll
        for (int nl = 0; nl < 4; ++nl)
            wv[nl] = __ldg(&WF4[((wc * 4 + nl) * 16 + q) * 32 + lane]);

        #pragma unroll
        for (int mt = 0; mt < 2; ++mt)
            #pragma unroll
            for (int nl = 0; nl < 4; ++nl)
                mma8(acc[mt][nl], ah[mt].x, ah[mt].y, ah[mt].z, ah[mt].w, wv[nl].x, wv[nl].y);
        #pragma unroll
        for (int mt = 0; mt < 2; ++mt)
            #pragma unroll
            for (int nl = 0; nl < 4; ++nl)
                mma8(acc[mt][nl], al[mt].x, al[mt].y, al[mt].z, al[mt].w, wv[nl].x, wv[nl].y);
        #pragma unroll
        for (int mt = 0; mt < 2; ++mt)
            #pragma unroll
            for (int nl = 0; nl < 4; ++nl)
                mma8(acc[mt][nl], ah[mt].x, ah[mt].y, ah[mt].z, ah[mt].w, wv[nl].z, wv[nl].w);
    }

    #pragma unroll
    for (int mt = 0; mt < 2; ++mt) {
        #pragma unroll
        for (int rh = 0; rh < 2; ++rh) {
            int rloc = wr * 32 + mt * 16 + (lane >> 2) + rh * 8;
            int m = m0 + rloc;
            if (m >= n) continue;
            float inv = 1.0f / fmaxf(sqrtf(ss[rloc]), 1e-12f);
            #pragma unroll
            for (int nl = 0; nl < 4; ++nl) {
                int col = (wc * 4 + nl) * 8 + ((lane & 3) << 1);
                float2 r;
                r.x = fmaxf(fmaf(acc[mt][nl][rh * 2 + 0], inv, B[col]), 0.f);
                r.y = fmaxf(fmaf(acc[mt][nl][rh * 2 + 1], inv, B[col + 1]), 0.f);
                *reinterpret_cast<float2*>(&H[(size_t)m * 128 + col]) = r;
            }
        }
    }
}

// =====================================================================
// fused fc, single pass: acc = H.W1^T + sqrt(G).W2^T ; OUT = act(acc+B1+B2)
// =====================================================================
template <int FOUT, bool RELU>
__global__ __launch_bounds__(256, 2)
void fc_gemm(const float* __restrict__ Hin, const float* __restrict__ G,
             const float* __restrict__ W1F, const float* __restrict__ W2F,
             const float* __restrict__ B1, const float* __restrict__ B2,
             float* __restrict__ OUT, int n)
{
    constexpr int NTW = FOUT / 32;
    extern __shared__ float sm[];
    float* AH = sm;
    float* AL = AH + 8192;
    float* GR = AL + 8192;

    const int tid = threadIdx.x;
    const int warp = tid >> 5, lane = tid & 31;
    const int m0 = blockIdx.x * 64;
    const int wr = warp >> 2, wc = warp & 3;

    stage_a<1, 0>(Hin, AH, AL, nullptr, tid, m0, n);
    stage_a<0, 1>(G, GR, nullptr, nullptr, tid, m0, n);
    __syncthreads();

    const float4* W1_4 = reinterpret_cast<const float4*>(W1F);
    const float4* W2_4 = reinterpret_cast<const float4*>(W2F);

    float acc[2][NTW][4];
    #pragma unroll
    for (int a = 0; a < 2; ++a)
        #pragma unroll
        for (int b = 0; b < NTW; ++b)
            #pragma unroll
            for (int c = 0; c < 4; ++c) acc[a][b][c] = 0.f;

    #pragma unroll 2
    for (int q = 0; q < 16; ++q) {
        float4 ah[2], al[2], gh[2], gl[2];
        #pragma unroll
        for (int mt = 0; mt < 2; ++mt) {
            int t = wr * 2 + mt;
            int off = (t * 16 + q) * 128 + lane * 4;
            ah[mt] = *reinterpret_cast<const float4*>(&AH[off]);
            al[mt] = *reinterpret_cast<const float4*>(&AL[off]);
            float4 g = *reinterpret_cast<const float4*>(&GR[off]);
            gh[mt].x = tf32_rna(g.x); gh[mt].y = tf32_rna(g.y);
            gh[mt].z = tf32_rna(g.z); gh[mt].w = tf32_rna(g.w);
            gl[mt].x = g.x - gh[mt].x; gl[mt].y = g.y - gh[mt].y;
            gl[mt].z = g.z - gh[mt].z; gl[mt].w = g.w - gh[mt].w;
        }
        float4 w1[NTW], w2[NTW];
        #pragma unroll
        for (int nl = 0; nl < NTW; ++nl) {
            int fi = ((wc * NTW + nl) * 16 + q) * 32 + lane;
            w1[nl] = __ldg(&W1_4[fi]);
            w2[nl] = __ldg(&W2_4[fi]);
        }
        #pragma unroll
        for (int mt = 0; mt < 2; ++mt)
            #pragma unroll
            for (int nl = 0; nl < NTW; ++nl)
                mma8(acc[mt][nl], ah[mt].x, ah[mt].y, ah[mt].z, ah[mt].w, w1[nl].x, w1[nl].y);
        #pragma unroll
        for (int mt = 0; mt < 2; ++mt)
            #pragma unroll
            for (int nl = 0; nl < NTW; ++nl)
                mma8(acc[mt][nl], gh[mt].x, gh[mt].y, gh[mt].z, gh[mt].w, w2[nl].x, w2[nl].y);
        #pragma unroll
        for (int mt = 0; mt < 2; ++mt)
            #pragma unroll
            for (int nl = 0; nl < NTW; ++nl)
                mma8(acc[mt][nl], al[mt].x, al[mt].y, al[mt].z, al[mt].w, w1[nl].x, w1[nl].y);
        #pragma unroll
        for (int mt = 0; mt < 2; ++mt)
            #pragma unroll
            for (int nl = 0; nl < NTW; ++nl)
                mma8(acc[mt][nl], gl[mt].x, gl[mt].y, gl[mt].z, gl[mt].w, w2[nl].x, w2[nl].y);
        #pragma unroll
        for (int mt = 0; mt < 2; ++mt)
            #pragma unroll
            for (int nl = 0; nl < NTW; ++nl)
                mma8(acc[mt][nl], ah[mt].x, ah[mt].y, ah[mt].z, ah[mt].w, w1[nl].z, w1[nl].w);
        #pragma unroll
        for (int mt = 0; mt < 2; ++mt)
            #pragma unroll
            for (int nl = 0; nl < NTW; ++nl)
                mma8(acc[mt][nl], gh[mt].x, gh[mt].y, gh[mt].z, gh[mt].w, w2[nl].z, w2[nl].w);
    }

    #pragma unroll
    for (int mt = 0; mt < 2; ++mt) {
        #pragma unroll
        for (int rh = 0; rh < 2; ++rh) {
            int rloc = wr * 32 + mt * 16 + (lane >> 2) + rh * 8;
            int m = m0 + rloc;
            if (m >= n) continue;
            #pragma unroll
            for (int nl = 0; nl < NTW; ++nl) {
                int col = (wc * NTW + nl) * 8 + ((lane & 3) << 1);
                float2 r;
                r.x = acc[mt][nl][rh * 2 + 0] + B1[col] + B2[col];
                r.y = acc[mt][nl][rh * 2 + 1] + B1[col + 1] + B2[col + 1];
                if (RELU) { r.x = fmaxf(r.x, 0.f); r.y = fmaxf(r.y, 0.f); }
                *reinterpret_cast<float2*>(&OUT[(size_t)m * FOUT + col]) = r;
            }
        }
    }
}

// =====================================================================
extern "C" void kernel_launch(void* const* d_in, const int* in_sizes, int n_in,
                              void* d_out, int out_size)
{
    const float* x     = (const float*)d_in[0];
    const int*   esrc  = (const int*)  d_in[1];
    const int*   edst  = (const int*)  d_in[2];
    const float* eval_ = (const float*)d_in[3];
    const float* pw0   = (const float*)d_in[4];
    const float* pb0   = (const float*)d_in[5];
    const float* f1w0  = (const float*)d_in[6];
    const float* f1b0  = (const float*)d_in[7];
    const float* f2w0  = (const float*)d_in[8];
    const float* f2b0  = (const float*)d_in[9];
    const float* pw1   = (const float*)d_in[10];
    const float* pb1   = (const float*)d_in[11];
    const float* f1w1  = (const float*)d_in[12];
    const float* f1b1  = (const float*)d_in[13];
    const float* f2w1  = (const float*)d_in[14];
    const float* f2b1  = (const float*)d_in[15];
    float* out = (float*)d_out;

    int n = in_sizes[0] / KD;
    int E = in_sizes[1];

    float *hP, *aP, *oP;
    float *wp0, *w10, *w20, *wp1, *w11, *w21;
    int *cntP, *rpP, *curP, *bsP, *boP;
    int2 *edP;
    cudaGetSymbolAddress((void**)&hP, g_h);
    cudaGetSymbolAddress((void**)&aP, g_agg);
    cudaGetSymbolAddress((void**)&oP, g_o0);
    cudaGetSymbolAddress((void**)&wp0, g_wfp0);
    cudaGetSymbolAddress((void**)&w10, g_wf10);
    cudaGetSymbolAddress((void**)&w20, g_wf20);
    cudaGetSymbolAddress((void**)&wp1, g_wfp1);
    cudaGetSymbolAddress((void**)&w11, g_wf11);
    cudaGetSymbolAddress((void**)&w21, g_wf21);
    cudaGetSymbolAddress((void**)&cntP, g_cnt);
    cudaGetSymbolAddress((void**)&rpP, g_rowptr);
    cudaGetSymbolAddress((void**)&curP, g_cursor);
    cudaGetSymbolAddress((void**)&bsP, g_bsum);
    cudaGetSymbolAddress((void**)&boP, g_boff);
    cudaGetSymbolAddress((void**)&edP, g_edata);

    const int POOL_SMEM = (8192 * 2 + 64) * 4;
    const int FC_SMEM   = (8192 * 3) * 4;
    cudaFuncSetAttribute(pool_gemm, cudaFuncAttributeMaxDynamicSharedMemorySize, POOL_SMEM);
    cudaFuncSetAttribute((const void*)fc_gemm<128, true>,
                         cudaFuncAttributeMaxDynamicSharedMemorySize, FC_SMEM);
    cudaFuncSetAttribute((const void*)fc_gemm<64, false>,
                         cudaFuncAttributeMaxDynamicSharedMemorySize, FC_SMEM);

    int mb = (n + 63) / 64;
    int gb = (n * 32 + 255) / 256;
    int nb = (n + SCAN_CH - 1) / SCAN_CH;    // <= 64

    // ---- weight splits + CSR build ----
    split_w6<<<dim3(32, 6), 256>>>(pw0, f1w0, f2w0, pw1, f1w1, f2w1,
                                   wp0, w10, w20, wp1, w11, w21);
    zero_cnt<<<(n + 255) / 256, 256>>>(cntP, n);
    hist_kernel<<<512, 512>>>(edst, cntP, E);
    scan_reduce<<<nb, 256>>>(cntP, bsP, n);
    scan_blocks<<<1, 64>>>(bsP, boP, rpP, nb, n);
    scan_final<<<nb, 256>>>(cntP, boP, rpP, curP, n);
    scatter_kernel<<<512, 512>>>(esrc, edst, eval_, curP, edP, E);

    // ---- layer 0 ----
    pool_gemm<<<mb, 256, POOL_SMEM>>>(x, wp0, pb0, hP, n);
    spmm_gather<<<gb, 256>>>(edP, rpP, hP, aP, n);
    fc_gemm<128, true><<<mb, 256, FC_SMEM>>>(hP, aP, w10, w20, f1b0, f2b0, oP, n);

    // ---- layer 1 ----
    pool_gemm<<<mb, 256, POOL_SMEM>>>(oP, wp1, pb1, hP, n);
    spmm_gather<<<gb, 256>>>(edP, rpP, hP, aP, n);
    fc_gemm<64, false><<<mb, 256, FC_SMEM>>>(hP, aP, w11, w21, f1b1, f2b1, out, n);
}

// round 10
// speedup vs baseline: 2.2990x; 1.0430x over previous
#include <cuda_runtime.h>
#include <math.h>

#define NMAX 50000
#define EMAX 800000
#define KD 128
#define SCAN_CH 1024

__device__ float g_h[(size_t)NMAX * KD];
__device__ float g_agg[(size_t)NMAX * KD];
__device__ float g_o0[(size_t)NMAX * KD];

// fragment-ordered split weights (hi/lo packed per float4)
__device__ float g_wfp0[32768];
__device__ float g_wf10[32768];
__device__ float g_wf20[32768];
__device__ float g_wfp1[32768];
__device__ float g_wf11[16384];
__device__ float g_wf21[16384];

// CSR scratch (built once per call, reused by both layers)
__device__ int  g_cnt[NMAX];
__device__ int  g_rowptr[NMAX + 1];
__device__ int  g_cursor[NMAX];
__device__ int  g_bsum[64];
__device__ int  g_boff[64];
__device__ int2 g_edata[EMAX];

// ---------------- tf32 helpers ----------------
__device__ __forceinline__ float tf32_rna(float x) {
    unsigned u;
    asm("cvt.rna.tf32.f32 %0, %1;" : "=r"(u) : "f"(x));
    return __uint_as_float(u);
}

__device__ __forceinline__ void mma8(float* d, float a0, float a1, float a2, float a3,
                                     float b0, float b1)
{
    asm("mma.sync.aligned.m16n8k8.row.col.f32.tf32.tf32.f32 "
        "{%0,%1,%2,%3}, {%4,%5,%6,%7}, {%8,%9}, {%0,%1,%2,%3};"
        : "+f"(d[0]), "+f"(d[1]), "+f"(d[2]), "+f"(d[3])
        : "r"(__float_as_uint(a0)), "r"(__float_as_uint(a1)),
          "r"(__float_as_uint(a2)), "r"(__float_as_uint(a3)),
          "r"(__float_as_uint(b0)), "r"(__float_as_uint(b1)));
}

// =====================================================================
// all 6 weight splits in ONE launch (blockIdx.y = job)
// =====================================================================
__global__ void split_w6(const float* __restrict__ w0, const float* __restrict__ w1,
                         const float* __restrict__ w2, const float* __restrict__ w3,
                         const float* __restrict__ w4, const float* __restrict__ w5,
                         float* o0, float* o1, float* o2, float* o3, float* o4, float* o5)
{
    int j = blockIdx.y;
    const float* W;
    float* WF;
    int total;
    switch (j) {
        case 0: W = w0; WF = o0; total = 8192; break;
        case 1: W = w1; WF = o1; total = 8192; break;
        case 2: W = w2; WF = o2; total = 8192; break;
        case 3: W = w3; WF = o3; total = 8192; break;
        case 4: W = w4; WF = o4; total = 4096; break;
        default: W = w5; WF = o5; total = 4096; break;
    }
    int idx = blockIdx.x * 256 + threadIdx.x;
    if (idx >= total) return;
    int lane = idx & 31, blk = idx >> 5;
    int q = blk & 15, nt = blk >> 4;
    int n = nt * 8 + (lane >> 2), k = q * 8 + (lane & 3);
    float v0 = W[n * 128 + k], v1 = W[n * 128 + k + 4];
    float h0 = tf32_rna(v0), h1 = tf32_rna(v1);
    reinterpret_cast<float4*>(WF)[idx] = make_float4(h0, h1, v0 - h0, v1 - h1);
}

// ===================== CSR build =====================
__global__ void zero_cnt(int* __restrict__ cnt, int n)
{
    int i = blockIdx.x * blockDim.x + threadIdx.x;
    if (i < n) cnt[i] = 0;
}

__global__ void hist_kernel(const int* __restrict__ dst, int* __restrict__ cnt, int E)
{
    int i = blockIdx.x * blockDim.x + threadIdx.x;
    int stride = gridDim.x * blockDim.x;
    for (; i < E; i += stride) atomicAdd(&cnt[dst[i]], 1);
}

__global__ void scan_reduce(const int* __restrict__ cnt, int* __restrict__ bsum, int n)
{
    __shared__ int wsum[8];
    const int tid = threadIdx.x, lane = tid & 31, wid = tid >> 5;
    int base = blockIdx.x * SCAN_CH + tid * 4;
    int s = 0;
    #pragma unroll
    for (int j = 0; j < 4; ++j) {
        int i = base + j;
        s += (i < n) ? cnt[i] : 0;
    }
    #pragma unroll
    for (int off = 16; off > 0; off >>= 1)
        s += __shfl_xor_sync(0xffffffffu, s, off);
    if (lane == 0) wsum[wid] = s;
    __syncthreads();
    if (tid == 0) {
        int t = 0;
        #pragma unroll
        for (int w = 0; w < 8; ++w) t += wsum[w];
        bsum[blockIdx.x] = t;
    }
}

__global__ void scan_blocks(const int* __restrict__ bsum, int* __restrict__ boff,
                            int* __restrict__ rowptr, int nb, int n)
{
    const int tid = threadIdx.x;   // 64 threads
    __shared__ int tmp[64];
    int v = (tid < nb) ? bsum[tid] : 0;
    tmp[tid] = v;
    __syncthreads();
    if (tid == 0) {
        int run = 0;
        for (int i = 0; i < nb; ++i) { int c = tmp[i]; tmp[i] = run; run += c; }
        rowptr[n] = run;
    }
    __syncthreads();
    if (tid < nb) boff[tid] = tmp[tid];
}

__global__ void scan_final(const int* __restrict__ cnt, const int* __restrict__ boff,
                           int* __restrict__ rowptr, int* __restrict__ cursor, int n)
{
    __shared__ int wsum[8];
    const int tid = threadIdx.x, lane = tid & 31, wid = tid >> 5;
    int base = blockIdx.x * SCAN_CH + tid * 4;
    int c[4];
    int tsum = 0;
    #pragma unroll
    for (int j = 0; j < 4; ++j) {
        int i = base + j;
        c[j] = (i < n) ? cnt[i] : 0;
        tsum += c[j];
    }
    int x = tsum;
    #pragma unroll
    for (int off = 1; off < 32; off <<= 1) {
        int t = __shfl_up_sync(0xffffffffu, x, off);
        if (lane >= off) x += t;
    }
    if (lane == 31) wsum[wid] = x;
    __syncthreads();
    if (wid == 0 && lane < 8) {
        int y = wsum[lane];
        #pragma unroll
        for (int off = 1; off < 8; off <<= 1) {
            int t = __shfl_up_sync(0xffu, y, off);
            if (lane >= off) y += t;
        }
        wsum[lane] = y;
    }
    __syncthreads();
    int run = x - tsum + (wid ? wsum[wid - 1] : 0) + boff[blockIdx.x];
    #pragma unroll
    for (int j = 0; j < 4; ++j) {
        int i = base + j;
        if (i < n) { rowptr[i] = run; cursor[i] = run; }
        run += c[j];
    }
}

__global__ void scatter_kernel(const int* __restrict__ src, const int* __restrict__ dst,
                               const float* __restrict__ val, int* __restrict__ cursor,
                               int2* __restrict__ edata, int E)
{
    int i = blockIdx.x * blockDim.x + threadIdx.x;
    int stride = gridDim.x * blockDim.x;
    for (; i < E; i += stride) {
        int d = dst[i];
        int pos = atomicAdd(&cursor[d], 1);
        edata[pos] = make_int2(src[i], __float_as_int(val[i]));
    }
}

// =====================================================================
// SpMM gather: AGG[r,:] = sum_{e in row r} val_e * H[src_e,:]^2
// one warp per dst row; 4-edge unrolled for MLP
// =====================================================================
__global__ __launch_bounds__(256)
void spmm_gather(const int2* __restrict__ edata, const int* __restrict__ rowptr,
                 const float* __restrict__ Hm, float* __restrict__ AGG, int n)
{
    int gw = (int)((blockIdx.x * 256u + threadIdx.x) >> 5);
    int lane = threadIdx.x & 31;
    if (gw >= n) return;
    int e0 = rowptr[gw], e1 = rowptr[gw + 1];
    const float4* H4 = reinterpret_cast<const float4*>(Hm);
    float4 acc = make_float4(0.f, 0.f, 0.f, 0.f);
    int e = e0;
    for (; e + 3 < e1; e += 4) {
        int2 ea = __ldg(&edata[e]);
        int2 eb = __ldg(&edata[e + 1]);
        int2 ec = __ldg(&edata[e + 2]);
        int2 ed = __ldg(&edata[e + 3]);
        float4 ha = __ldg(&H4[(size_t)ea.x * 32 + lane]);
        float4 hb = __ldg(&H4[(size_t)eb.x * 32 + lane]);
        float4 hc = __ldg(&H4[(size_t)ec.x * 32 + lane]);
        float4 hd = __ldg(&H4[(size_t)ed.x * 32 + lane]);
        float va = __int_as_float(ea.y), vb = __int_as_float(eb.y);
        float vc = __int_as_float(ec.y), vd = __int_as_float(ed.y);
        acc.x = fmaf(va * ha.x, ha.x, acc.x);
        acc.y = fmaf(va * ha.y, ha.y, acc.y);
        acc.z = fmaf(va * ha.z, ha.z, acc.z);
        acc.w = fmaf(va * ha.w, ha.w, acc.w);
        acc.x = fmaf(vb * hb.x, hb.x, acc.x);
        acc.y = fmaf(vb * hb.y, hb.y, acc.y);
        acc.z = fmaf(vb * hb.z, hb.z, acc.z);
        acc.w = fmaf(vb * hb.w, hb.w, acc.w);
        acc.x = fmaf(vc * hc.x, hc.x, acc.x);
        acc.y = fmaf(vc * hc.y, hc.y, acc.y);
        acc.z = fmaf(vc * hc.z, hc.z, acc.z);
        acc.w = fmaf(vc * hc.w, hc.w, acc.w);
        acc.x = fmaf(vd * hd.x, hd.x, acc.x);
        acc.y = fmaf(vd * hd.y, hd.y, acc.y);
        acc.z = fmaf(vd * hd.z, hd.z, acc.z);
        acc.w = fmaf(vd * hd.w, hd.w, acc.w);
    }
    for (; e < e1; ++e) {
        int2 ea = __ldg(&edata[e]);
        float va = __int_as_float(ea.y);
        float4 ha = __ldg(&H4[(size_t)ea.x * 32 + lane]);
        acc.x = fmaf(va * ha.x, ha.x, acc.x);
        acc.y = fmaf(va * ha.y, ha.y, acc.y);
        acc.z = fmaf(va * ha.z, ha.z, acc.z);
        acc.w = fmaf(va * ha.w, ha.w, acc.w);
    }
    reinterpret_cast<float4*>(AGG)[(size_t)gw * 32 + lane] = acc;
}

// ---- stage A rows [64][128] into fragment layout ----
template <int SPLIT, int MODE>
__device__ __forceinline__ void stage_a(const float* __restrict__ Ain, float* __restrict__ AH,
                                        float* __restrict__ AL, float* __restrict__ sumsq,
                                        int tid, int m0, int n)
{
    float part = 0.f;
    int row = tid & 63;
    #pragma unroll
    for (int it = 0; it < 8; ++it) {
        int l = (tid >> 6) + it * 4;
        int m = m0 + row;
        float4 v = make_float4(0.f, 0.f, 0.f, 0.f);
        if (m < n) v = reinterpret_cast<const float4*>(Ain)[(size_t)m * 32 + l];
        if (MODE == 1) {
            v.x = sqrtf(v.x); v.y = sqrtf(v.y); v.z = sqrtf(v.z); v.w = sqrtf(v.w);
        }
        if (MODE == 2)
            part += v.x * v.x + v.y * v.y + v.z * v.z + v.w * v.w;
        int t = row >> 4, r = row & 15;
        int q = l >> 1;
        int slot = (r >> 3) + ((l & 1) << 1);
        int base = (t * 16 + q) * 128 + ((r & 7) << 4) + slot;
        float vv[4] = {v.x, v.y, v.z, v.w};
        #pragma unroll
        for (int j = 0; j < 4; ++j) {
            if (SPLIT) {
                float hi = tf32_rna(vv[j]);
                AH[base + j * 4] = hi;
                AL[base + j * 4] = vv[j] - hi;
            } else {
                AH[base + j * 4] = vv[j];
            }
        }
    }
    if (MODE == 2) atomicAdd(&sumsq[row], part);
}

// =====================================================================
// pool GEMM + fused L2-norm + relu.
// =====================================================================
__global__ __launch_bounds__(256, 2)
void pool_gemm(const float* __restrict__ X, const float* __restrict__ WF,
               const float* __restrict__ B, float* __restrict__ H, int n)
{
    extern __shared__ float sm[];
    float* AH = sm;
    float* AL = AH + 8192;
    float* ss = AL + 8192;

    const int tid = threadIdx.x;
    const int warp = tid >> 5, lane = tid & 31;
    const int m0 = blockIdx.x * 64;

    if (tid < 64) ss[tid] = 0.f;
    __syncthreads();
    stage_a<1, 2>(X, AH, AL, ss, tid, m0, n);
    __syncthreads();

    const int wr = warp >> 2, wc = warp & 3;
    const float4* WF4 = reinterpret_cast<const float4*>(WF);

    float acc[2][4][4];
    #pragma unroll
    for (int a = 0; a < 2; ++a)
        #pragma unroll
        for (int b = 0; b < 4; ++b)
            #pragma unroll
            for (int c = 0; c < 4; ++c) acc[a][b][c] = 0.f;

    #pragma unroll 2
    for (int q = 0; q < 16; ++q) {
        float4 ah[2], al[2];
        #pragma unroll
        for (int mt = 0; mt < 2; ++mt) {
            int t = wr * 2 + mt;
            ah[mt] = *reinterpret_cast<const float4*>(&AH[(t * 16 + q) * 128 + lane * 4]);
            al[mt] = *reinterpret_cast<const float4*>(&AL[(t * 16 + q) * 128 + lane * 4]);
        }
        float4 wv[4];
        #pragma unroll
        for (int nl = 0; nl < 4; ++nl)
            wv[nl] = __ldg(&WF4[((wc * 4 + nl) * 16 + q) * 32 + lane]);

        #pragma unroll
        for (int mt = 0; mt < 2; ++mt)
            #pragma unroll
            for (int nl = 0; nl < 4; ++nl)
                mma8(acc[mt][nl], ah[mt].x, ah[mt].y, ah[mt].z, ah[mt].w, wv[nl].x, wv[nl].y);
        #pragma unroll
        for (int mt = 0; mt < 2; ++mt)
            #pragma unroll
            for (int nl = 0; nl < 4; ++nl)
                mma8(acc[mt][nl], al[mt].x, al[mt].y, al[mt].z, al[mt].w, wv[nl].x, wv[nl].y);
        #pragma unroll
        for (int mt = 0; mt < 2; ++mt)
            #pragma unroll
            for (int nl = 0; nl < 4; ++nl)
                mma8(acc[mt][nl], ah[mt].x, ah[mt].y, ah[mt].z, ah[mt].w, wv[nl].z, wv[nl].w);
    }

    #pragma unroll
    for (int mt = 0; mt < 2; ++mt) {
        #pragma unroll
        for (int rh = 0; rh < 2; ++rh) {
            int rloc = wr * 32 + mt * 16 + (lane >> 2) + rh * 8;
            int m = m0 + rloc;
            if (m >= n) continue;
            float inv = 1.0f / fmaxf(sqrtf(ss[rloc]), 1e-12f);
            #pragma unroll
            for (int nl = 0; nl < 4; ++nl) {
                int col = (wc * 4 + nl) * 8 + ((lane & 3) << 1);
                float2 r;
                r.x = fmaxf(fmaf(acc[mt][nl][rh * 2 + 0], inv, B[col]), 0.f);
                r.y = fmaxf(fmaf(acc[mt][nl][rh * 2 + 1], inv, B[col + 1]), 0.f);
                *reinterpret_cast<float2*>(&H[(size_t)m * 128 + col]) = r;
            }
        }
    }
}

// =====================================================================
// fused fc, single pass: acc = H.W1^T + sqrt(G).W2^T ; OUT = act(acc+B1+B2)
// =====================================================================
template <int FOUT, bool RELU>
__global__ __launch_bounds__(256, 2)
void fc_gemm(const float* __restrict__ Hin, const float* __restrict__ G,
             const float* __restrict__ W1F, const float* __restrict__ W2F,
             const float* __restrict__ B1, const float* __restrict__ B2,
             float* __restrict__ OUT, int n)
{
    constexpr int NTW = FOUT / 32;
    extern __shared__ float sm[];
    float* AH = sm;
    float* AL = AH + 8192;
    float* GR = AL + 8192;

    const int tid = threadIdx.x;
    const int warp = tid >> 5, lane = tid & 31;
    const int m0 = blockIdx.x * 64;
    const int wr = warp >> 2, wc = warp & 3;

    stage_a<1, 0>(Hin, AH, AL, nullptr, tid, m0, n);
    stage_a<0, 1>(G, GR, nullptr, nullptr, tid, m0, n);
    __syncthreads();

    const float4* W1_4 = reinterpret_cast<const float4*>(W1F);
    const float4* W2_4 = reinterpret_cast<const float4*>(W2F);

    float acc[2][NTW][4];
    #pragma unroll
    for (int a = 0; a < 2; ++a)
        #pragma unroll
        for (int b = 0; b < NTW; ++b)
            #pragma unroll
            for (int c = 0; c < 4; ++c) acc[a][b][c] = 0.f;

    #pragma unroll 2
    for (int q = 0; q < 16; ++q) {
        float4 ah[2], al[2], gh[2], gl[2];
        #pragma unroll
        for (int mt = 0; mt < 2; ++mt) {
            int t = wr * 2 + mt;
            int off = (t * 16 + q) * 128 + lane * 4;
            ah[mt] = *reinterpret_cast<const float4*>(&AH[off]);
            al[mt] = *reinterpret_cast<const float4*>(&AL[off]);
            float4 g = *reinterpret_cast<const float4*>(&GR[off]);
            gh[mt].x = tf32_rna(g.x); gh[mt].y = tf32_rna(g.y);
            gh[mt].z = tf32_rna(g.z); gh[mt].w = tf32_rna(g.w);
            gl[mt].x = g.x - gh[mt].x; gl[mt].y = g.y - gh[mt].y;
            gl[mt].z = g.z - gh[mt].z; gl[mt].w = g.w - gh[mt].w;
        }
        float4 w1[NTW], w2[NTW];
        #pragma unroll
        for (int nl = 0; nl < NTW; ++nl) {
            int fi = ((wc * NTW + nl) * 16 + q) * 32 + lane;
            w1[nl] = __ldg(&W1_4[fi]);
            w2[nl] = __ldg(&W2_4[fi]);
        }
        #pragma unroll
        for (int mt = 0; mt < 2; ++mt)
            #pragma unroll
            for (int nl = 0; nl < NTW; ++nl)
                mma8(acc[mt][nl], ah[mt].x, ah[mt].y, ah[mt].z, ah[mt].w, w1[nl].x, w1[nl].y);
        #pragma unroll
        for (int mt = 0; mt < 2; ++mt)
            #pragma unroll
            for (int nl = 0; nl < NTW; ++nl)
                mma8(acc[mt][nl], gh[mt].x, gh[mt].y, gh[mt].z, gh[mt].w, w2[nl].x, w2[nl].y);
        #pragma unroll
        for (int mt = 0; mt < 2; ++mt)
            #pragma unroll
            for (int nl = 0; nl < NTW; ++nl)
                mma8(acc[mt][nl], al[mt].x, al[mt].y, al[mt].z, al[mt].w, w1[nl].x, w1[nl].y);
        #pragma unroll
        for (int mt = 0; mt < 2; ++mt)
            #pragma unroll
            for (int nl = 0; nl < NTW; ++nl)
                mma8(acc[mt][nl], gl[mt].x, gl[mt].y, gl[mt].z, gl[mt].w, w2[nl].x, w2[nl].y);
        #pragma unroll
        for (int mt = 0; mt < 2; ++mt)
            #pragma unroll
            for (int nl = 0; nl < NTW; ++nl)
                mma8(acc[mt][nl], ah[mt].x, ah[mt].y, ah[mt].z, ah[mt].w, w1[nl].z, w1[nl].w);
        #pragma unroll
        for (int mt = 0; mt < 2; ++mt)
            #pragma unroll
            for (int nl = 0; nl < NTW; ++nl)
                mma8(acc[mt][nl], gh[mt].x, gh[mt].y, gh[mt].z, gh[mt].w, w2[nl].z, w2[nl].w);
    }

    #pragma unroll
    for (int mt = 0; mt < 2; ++mt) {
        #pragma unroll
        for (int rh = 0; rh < 2; ++rh) {
            int rloc = wr * 32 + mt * 16 + (lane >> 2) + rh * 8;
            int m = m0 + rloc;
            if (m >= n) continue;
            #pragma unroll
            for (int nl = 0; nl < NTW; ++nl) {
                int col = (wc * NTW + nl) * 8 + ((lane & 3) << 1);
                float2 r;
                r.x = acc[mt][nl][rh * 2 + 0] + B1[col] + B2[col];
                r.y = acc[mt][nl][rh * 2 + 1] + B1[col + 1] + B2[col + 1];
                if (RELU) { r.x = fmaxf(r.x, 0.f); r.y = fmaxf(r.y, 0.f); }
                *reinterpret_cast<float2*>(&OUT[(size_t)m * FOUT + col]) = r;
            }
        }
    }
}

// =====================================================================
extern "C" void kernel_launch(void* const* d_in, const int* in_sizes, int n_in,
                              void* d_out, int out_size)
{
    const float* x     = (const float*)d_in[0];
    const int*   esrc  = (const int*)  d_in[1];
    const int*   edst  = (const int*)  d_in[2];
    const float* eval_ = (const float*)d_in[3];
    const float* pw0   = (const float*)d_in[4];
    const float* pb0   = (const float*)d_in[5];
    const float* f1w0  = (const float*)d_in[6];
    const float* f1b0  = (const float*)d_in[7];
    const float* f2w0  = (const float*)d_in[8];
    const float* f2b0  = (const float*)d_in[9];
    const float* pw1   = (const float*)d_in[10];
    const float* pb1   = (const float*)d_in[11];
    const float* f1w1  = (const float*)d_in[12];
    const float* f1b1  = (const float*)d_in[13];
    const float* f2w1  = (const float*)d_in[14];
    const float* f2b1  = (const float*)d_in[15];
    float* out = (float*)d_out;

    int n = in_sizes[0] / KD;
    int E = in_sizes[1];

    float *hP, *aP, *oP;
    float *wp0, *w10, *w20, *wp1, *w11, *w21;
    int *cntP, *rpP, *curP, *bsP, *boP;
    int2 *edP;
    cudaGetSymbolAddress((void**)&hP, g_h);
    cudaGetSymbolAddress((void**)&aP, g_agg);
    cudaGetSymbolAddress((void**)&oP, g_o0);
    cudaGetSymbolAddress((void**)&wp0, g_wfp0);
    cudaGetSymbolAddress((void**)&w10, g_wf10);
    cudaGetSymbolAddress((void**)&w20, g_wf20);
    cudaGetSymbolAddress((void**)&wp1, g_wfp1);
    cudaGetSymbolAddress((void**)&w11, g_wf11);
    cudaGetSymbolAddress((void**)&w21, g_wf21);
    cudaGetSymbolAddress((void**)&cntP, g_cnt);
    cudaGetSymbolAddress((void**)&rpP, g_rowptr);
    cudaGetSymbolAddress((void**)&curP, g_cursor);
    cudaGetSymbolAddress((void**)&bsP, g_bsum);
    cudaGetSymbolAddress((void**)&boP, g_boff);
    cudaGetSymbolAddress((void**)&edP, g_edata);

    const int POOL_SMEM = (8192 * 2 + 64) * 4;
    const int FC_SMEM   = (8192 * 3) * 4;
    cudaFuncSetAttribute(pool_gemm, cudaFuncAttributeMaxDynamicSharedMemorySize, POOL_SMEM);
    cudaFuncSetAttribute((const void*)fc_gemm<128, true>,
                         cudaFuncAttributeMaxDynamicSharedMemorySize, FC_SMEM);
    cudaFuncSetAttribute((const void*)fc_gemm<64, false>,
                         cudaFuncAttributeMaxDynamicSharedMemorySize, FC_SMEM);

    int mb = (n + 63) / 64;
    int gb = (n * 32 + 255) / 256;
    int nb = (n + SCAN_CH - 1) / SCAN_CH;    // <= 64

    // fork/join: CSR build runs on a side stream, concurrent with
    // split_w6 + layer-0 pool_gemm on the main (capture) stream.
    cudaStream_t s2;
    cudaStreamCreate(&s2);
    cudaEvent_t evFork, evJoin;
    cudaEventCreateWithFlags(&evFork, cudaEventDisableTiming);
    cudaEventCreateWithFlags(&evJoin, cudaEventDisableTiming);

    cudaEventRecord(evFork, 0);
    cudaStreamWaitEvent(s2, evFork, 0);

    // ---- side stream: CSR build ----
    zero_cnt<<<(n + 255) / 256, 256, 0, s2>>>(cntP, n);
    hist_kernel<<<512, 512, 0, s2>>>(edst, cntP, E);
    scan_reduce<<<nb, 256, 0, s2>>>(cntP, bsP, n);
    scan_blocks<<<1, 64, 0, s2>>>(bsP, boP, rpP, nb, n);
    scan_final<<<nb, 256, 0, s2>>>(cntP, boP, rpP, curP, n);
    scatter_kernel<<<512, 512, 0, s2>>>(esrc, edst, eval_, curP, edP, E);
    cudaEventRecord(evJoin, s2);

    // ---- main stream: weight splits + layer-0 pool ----
    split_w6<<<dim3(32, 6), 256>>>(pw0, f1w0, f2w0, pw1, f1w1, f2w1,
                                   wp0, w10, w20, wp1, w11, w21);
    pool_gemm<<<mb, 256, POOL_SMEM>>>(x, wp0, pb0, hP, n);

    // join: spmm needs both hP (main) and CSR (side)
    cudaStreamWaitEvent(0, evJoin, 0);

    spmm_gather<<<gb, 256>>>(edP, rpP, hP, aP, n);
    fc_gemm<128, true><<<mb, 256, FC_SMEM>>>(hP, aP, w10, w20, f1b0, f2b0, oP, n);

    // ---- layer 1 ----
    pool_gemm<<<mb, 256, POOL_SMEM>>>(oP, wp1, pb1, hP, n);
    spmm_gather<<<gb, 256>>>(edP, rpP, hP, aP, n);
    fc_gemm<64, false><<<mb, 256, FC_SMEM>>>(hP, aP, w11, w21, f1b1, f2b1, out, n);
}